// round 7
// baseline (speedup 1.0000x reference)
#include <cuda_runtime.h>
#include <cuda_bf16.h>
#include <math.h>
#include <stdint.h>

// Problem constants
#define LAYERS 4
#define D_     128
#define N_     2048
#define TWON   4096
#define INV_T  5.0f
#define EPS    1e-12f
#define C_EX2  7.21347520444481703076f   // (1/T) * log2(e)

#define NCHUNK 32          // 4096 / 128 cols per chunk
#define CHUNK  128
#define SROWB  272         // smem row stride bytes (128 bf16 + 16B pad)
#define TILEB  (128 * SROWB)
#define NBUF   3

// Scratch
__device__ __align__(256) __nv_bfloat16 g_zb[LAYERS * TWON * D_];
__device__ float g_lp[LAYERS * TWON];

// ---------------------------------------------------------------------------
__device__ __forceinline__ uint32_t smem_u32(const void* p) {
    uint32_t a;
    asm("{ .reg .u64 t; cvta.to.shared.u64 t, %1; cvt.u32.u64 %0, t; }" : "=r"(a) : "l"(p));
    return a;
}
__device__ __forceinline__ float ex2f(float x) {
    float r; asm("ex2.approx.ftz.f32 %0, %1;" : "=f"(r) : "f"(x)); return r;
}
#define CP_ASYNC16(dst, src) \
    asm volatile("cp.async.cg.shared.global [%0], [%1], 16;" :: "r"(dst), "l"(src))
#define CP_COMMIT() asm volatile("cp.async.commit_group;" ::: "memory")
#define CP_WAIT(n)  asm volatile("cp.async.wait_group %0;" :: "n"(n) : "memory")

__device__ __forceinline__ void ldsm4(uint32_t* r, uint32_t addr) {
    asm volatile("ldmatrix.sync.aligned.m8n8.x4.shared.b16 {%0,%1,%2,%3}, [%4];"
                 : "=r"(r[0]), "=r"(r[1]), "=r"(r[2]), "=r"(r[3]) : "r"(addr));
}
__device__ __forceinline__ void mma_bf16(float* c, const uint32_t* a, const uint32_t* b) {
    asm volatile(
        "mma.sync.aligned.m16n8k16.row.col.f32.bf16.bf16.f32 "
        "{%0,%1,%2,%3}, {%4,%5,%6,%7}, {%8,%9}, {%0,%1,%2,%3};"
        : "+f"(c[0]), "+f"(c[1]), "+f"(c[2]), "+f"(c[3])
        : "r"(a[0]), "r"(a[1]), "r"(a[2]), "r"(a[3]), "r"(b[0]), "r"(b[1]));
}

// ---------------------------------------------------------------------------
// Kernel 1: L2-normalize -> bf16. One warp per row.
// ---------------------------------------------------------------------------
__global__ void norm_bf16_kernel(const float* __restrict__ emb_i,
                                 const float* __restrict__ emb_j) {
    int warp = (blockIdx.x * blockDim.x + threadIdx.x) >> 5;
    int lane = threadIdx.x & 31;
    if (warp >= LAYERS * TWON) return;
    int layer = warp >> 12;
    int row   = warp & (TWON - 1);

    const float* src = (row < N_)
        ? (emb_i + ((size_t)layer * N_ + row) * D_)
        : (emb_j + ((size_t)layer * N_ + (row - N_)) * D_);

    float4 v = ((const float4*)src)[lane];
    float s = v.x * v.x + v.y * v.y + v.z * v.z + v.w * v.w;
    #pragma unroll
    for (int o = 16; o > 0; o >>= 1) s += __shfl_xor_sync(0xffffffffu, s, o);

    float inv = 1.0f / fmaxf(sqrtf(s), EPS);
    uint2 u;
    u.x = (uint32_t)__bfloat16_as_ushort(__float2bfloat16(v.x * inv))
        | ((uint32_t)__bfloat16_as_ushort(__float2bfloat16(v.y * inv)) << 16);
    u.y = (uint32_t)__bfloat16_as_ushort(__float2bfloat16(v.z * inv))
        | ((uint32_t)__bfloat16_as_ushort(__float2bfloat16(v.w * inv)) << 16);
    ((uint2*)(g_zb + ((size_t)layer * TWON + row) * D_))[lane] = u;
}

// ---------------------------------------------------------------------------
// Kernel 2: fused Gram + exp + row reduction (mma.sync bf16).
// Grid = LAYERS*32; block = 256 (8 warps, 4x2 warp grid: m_w=32, n_w=64).
// A fragments register-resident. B streamed via 3-buffer cp.async ring.
// NEW: per-chunk software pipeline over 16-col groups np:
//   mma(0); mma(1); epi(0); mma(2); epi(1); mma(3); epi(2); epi(3)
// so EX2/FMA of group np-1 interleaves with HMMA/LDSM of group np.
// ---------------------------------------------------------------------------
extern __shared__ char dsm[];

__device__ __forceinline__ void load_tile(const __nv_bfloat16* Z, int rowBase,
                                          uint32_t base, int tid) {
    #pragma unroll
    for (int i = 0; i < 8; ++i) {
        int idx = i * 256 + tid;
        int r = idx >> 4, sc = idx & 15;
        const char* src = (const char*)(Z + (size_t)(rowBase + r) * D_) + sc * 16;
        CP_ASYNC16(base + r * SROWB + sc * 16, src);
    }
}

// MMA for column group np (nt = 2np, 2np+1), all kt.
__device__ __forceinline__ void mma_group(float (&acc)[2][8][4],
                                          const uint32_t (&aF)[2][8][4],
                                          uint32_t bA, int np) {
    #pragma unroll
    for (int kt = 0; kt < 8; ++kt) {
        uint32_t t[4];
        ldsm4(t, bA + (uint32_t)(np * 16 * SROWB + kt * 32));
        mma_bf16(acc[0][2 * np],     aF[0][kt], &t[0]);
        mma_bf16(acc[0][2 * np + 1], aF[0][kt], &t[2]);
        mma_bf16(acc[1][2 * np],     aF[1][kt], &t[0]);
        mma_bf16(acc[1][2 * np + 1], aF[1][kt], &t[2]);
    }
}

// Epilogue for column group np: exp-accumulate, optional diag/pos capture, rezero.
__device__ __forceinline__ void epi_group(float (&acc)[2][8][4], int np, bool chk,
                                          int cb, int rowT, int colTbase,
                                          float* dsum, float* sdg, float* sps) {
    #pragma unroll
    for (int nn = 0; nn < 2; ++nn) {
        int nt = 2 * np + nn;
        #pragma unroll
        for (int mt = 0; mt < 2; ++mt)
            #pragma unroll
            for (int ci = 0; ci < 4; ++ci) {
                float s = acc[mt][nt][ci];
                int ri = mt * 2 + (ci >> 1);
                dsum[ri] += ex2f(s * C_EX2);
                if (chk) {
                    int grow = rowT + mt * 16 + (ci >> 1) * 8;
                    int gcol = cb + colTbase + nt * 8 + (ci & 1);
                    if (gcol == grow)        sdg[ri] = s;
                    if (gcol == (grow ^ N_)) sps[ri] = s;
                }
                acc[mt][nt][ci] = 0.f;
            }
    }
}

__global__ void __launch_bounds__(256, 1) sim_mma_kernel() {
    __shared__ float red_d[2][128];
    __shared__ float red_g[2][128];
    __shared__ float red_p[2][128];

    int tid  = threadIdx.x;
    int wid  = tid >> 5;
    int lane = tid & 31;
    int warpRow = wid & 3;      // 4 row slices of 32
    int warpCol = wid >> 2;     // 2 col slices of 64

    int layer   = blockIdx.x >> 5;
    int tile    = blockIdx.x & 31;
    int rowBase = tile * CHUNK;
    const __nv_bfloat16* Z = g_zb + (size_t)layer * TWON * D_;

    uint32_t sb = (smem_u32(dsm) + 1023) & ~1023u;
    uint32_t aBase = sb;
    uint32_t bBase[NBUF] = { sb + TILEB, sb + 2 * TILEB, sb + 3 * TILEB };

    // Prologue: A tile (group0) then B chunk 0 (group1)
    load_tile(Z, rowBase, aBase, tid);
    CP_COMMIT();
    load_tile(Z, 0, bBase[0], tid);
    CP_COMMIT();

    uint32_t laneA = (uint32_t)((lane & 7) * SROWB + ((lane >> 3) & 1) * (8 * SROWB)
                                + ((lane >> 4) & 1) * 16);
    uint32_t laneB = (uint32_t)((lane & 7) * SROWB + ((lane >> 3) & 1) * 16
                                + ((lane >> 4) & 1) * (8 * SROWB));
    uint32_t aAddr = aBase + (uint32_t)(warpRow * 32 * SROWB) + laneA;

    CP_WAIT(1);                 // A done
    __syncthreads();

    // A fragments -> registers (64 regs), reused across all 32 chunks
    uint32_t aF[2][8][4];
    #pragma unroll
    for (int mt = 0; mt < 2; ++mt)
        #pragma unroll
        for (int kt = 0; kt < 8; ++kt)
            ldsm4(aF[mt][kt], aAddr + (uint32_t)(mt * 16 * SROWB + kt * 32));

    float acc[2][8][4];
    #pragma unroll
    for (int mt = 0; mt < 2; ++mt)
        #pragma unroll
        for (int nt = 0; nt < 8; ++nt)
            #pragma unroll
            for (int ci = 0; ci < 4; ++ci) acc[mt][nt][ci] = 0.f;

    float dsum[4], sdg[4], sps[4];
    #pragma unroll
    for (int i = 0; i < 4; ++i) { dsum[i] = 0.f; sdg[i] = 0.f; sps[i] = 0.f; }

    int rowT     = rowBase + warpRow * 32 + (lane >> 2);  // + mt*16 + 8*(ci>>1)
    int colTbase = warpCol * 64 + (lane & 3) * 2;         // + nt*8 + (ci&1) + cb

    for (int ct = 0; ct < NCHUNK; ++ct) {
        if (ct + 1 < NCHUNK) {
            load_tile(Z, (ct + 1) * CHUNK, bBase[(ct + 1) % NBUF], tid);
            CP_COMMIT();
            CP_WAIT(1);
        } else {
            CP_WAIT(0);
        }
        __syncthreads();       // B(ct) ready; fences prior-iteration reads

        uint32_t bA = bBase[ct % NBUF] + (uint32_t)(warpCol * 64 * SROWB) + laneB;
        int cb = ct * CHUNK;
        bool chk = (ct == tile) || (ct == (tile ^ (N_ / CHUNK)));

        // Software-pipelined: epi(np-1) overlaps mma(np)
        mma_group(acc, aF, bA, 0);
        mma_group(acc, aF, bA, 1);
        epi_group(acc, 0, chk, cb, rowT, colTbase, dsum, sdg, sps);
        mma_group(acc, aF, bA, 2);
        epi_group(acc, 1, chk, cb, rowT, colTbase, dsum, sdg, sps);
        mma_group(acc, aF, bA, 3);
        epi_group(acc, 2, chk, cb, rowT, colTbase, dsum, sdg, sps);
        epi_group(acc, 3, chk, cb, rowT, colTbase, dsum, sdg, sps);
    }

    // Reduce across lane&3 (4 lanes covering col groups)
    #pragma unroll
    for (int ri = 0; ri < 4; ++ri) {
        #pragma unroll
        for (int o = 1; o <= 2; o <<= 1) {
            dsum[ri] += __shfl_xor_sync(0xffffffffu, dsum[ri], o);
            sdg[ri]  += __shfl_xor_sync(0xffffffffu, sdg[ri], o);
            sps[ri]  += __shfl_xor_sync(0xffffffffu, sps[ri], o);
        }
    }
    if ((lane & 3) == 0) {
        #pragma unroll
        for (int ri = 0; ri < 4; ++ri) {
            int mt = ri >> 1, h = ri & 1;
            int rloc = warpRow * 32 + mt * 16 + h * 8 + (lane >> 2);
            red_d[warpCol][rloc] = dsum[ri];
            red_g[warpCol][rloc] = sdg[ri];
            red_p[warpCol][rloc] = sps[ri];
        }
    }
    __syncthreads();

    if (tid < 128) {
        float d  = red_d[0][tid] + red_d[1][tid];
        float sg = red_g[0][tid] + red_g[1][tid];
        float sp = red_p[0][tid] + red_p[1][tid];
        float denom = d - ex2f(sg * C_EX2);   // exclude diagonal
        g_lp[layer * TWON + rowBase + tid] = logf(denom) - sp * INV_T;
    }
}

// ---------------------------------------------------------------------------
// Kernel 3: deterministic final reduction with joint_valid mask.
// ---------------------------------------------------------------------------
__global__ void finalize_kernel(const float* __restrict__ joint_valid,
                                float* __restrict__ out) {
    __shared__ float s1[256];
    __shared__ float s2[256];
    int tid = threadIdx.x;

    float total = 0.f;
    for (int idx = tid; idx < LAYERS * TWON; idx += 256) {
        int row = idx & (TWON - 1);
        total += g_lp[idx] * joint_valid[row & (N_ - 1)];
    }
    float an = 0.f;
    for (int idx = tid; idx < N_; idx += 256) an += joint_valid[idx];

    s1[tid] = total;
    s2[tid] = an;
    __syncthreads();
    for (int s = 128; s > 0; s >>= 1) {
        if (tid < s) { s1[tid] += s1[tid + s]; s2[tid] += s2[tid + s]; }
        __syncthreads();
    }
    if (tid == 0) out[0] = s1[0] / (2.0f * s2[0]);
}

// ---------------------------------------------------------------------------
extern "C" void kernel_launch(void* const* d_in, const int* in_sizes, int n_in,
                              void* d_out, int out_size) {
    const float* emb_i       = (const float*)d_in[0];
    const float* emb_j       = (const float*)d_in[1];
    const float* joint_valid = (const float*)d_in[2];
    float* out = (float*)d_out;
    (void)in_sizes; (void)n_in; (void)out_size;

    const int SIM_SMEM = 1024 + (1 + NBUF) * TILEB;   // A + 3 B buffers = 140288 B
    cudaFuncSetAttribute(sim_mma_kernel, cudaFuncAttributeMaxDynamicSharedMemorySize, SIM_SMEM);

    norm_bf16_kernel<<<(LAYERS * TWON) / 8, 256>>>(emb_i, emb_j);
    sim_mma_kernel<<<LAYERS * 32, 256, SIM_SMEM>>>();
    finalize_kernel<<<1, 256>>>(joint_valid, out);
}

// round 8
// speedup vs baseline: 1.0895x; 1.0895x over previous
#include <cuda_runtime.h>
#include <cuda_bf16.h>
#include <math.h>
#include <stdint.h>

// Problem constants
#define LAYERS 4
#define D_     128
#define N_     2048
#define TWON   4096
#define INV_T  5.0f
#define EPS    1e-12f
#define C_EX2  7.21347520444481703076f   // (1/T) * log2(e)
#define SQC    2.68579079f               // sqrt(C_EX2); z stored as z*SQC => acc = C_EX2*s
#define LN2F   0.69314718056f            // INV_T / C_EX2

#define SROWB  272                       // smem row stride bytes (128 bf16 + 16B pad)
#define TILEB  (128 * SROWB)             // 34816
#define NTILE  32                        // 4096/128 blocks per layer
#define TOPSL  528                       // NTILE*(NTILE+1)/2 tile-ops per layer
#define NCTA   132                       // 2112 total tile-ops / 132 = 16 each
#define TOPC   16                        // tile-ops per CTA

// Scratch
__device__ __align__(256) __nv_bfloat16 g_zb[LAYERS * TWON * D_];
__device__ float g_acc[LAYERS * NTILE * NTILE * 128];  // [l][i][j][rl] exp-sums (2MB)
__device__ float g_diag[LAYERS * TWON];                // scaled diag acc (C*s_ii)
__device__ float g_posv[LAYERS * N_];                  // scaled pos acc (C*s_pos)
__device__ float g_lp[LAYERS * TWON];

// ---------------------------------------------------------------------------
__device__ __forceinline__ uint32_t smem_u32(const void* p) {
    uint32_t a;
    asm("{ .reg .u64 t; cvta.to.shared.u64 t, %1; cvt.u32.u64 %0, t; }" : "=r"(a) : "l"(p));
    return a;
}
__device__ __forceinline__ float ex2f(float x) {
    float r; asm("ex2.approx.ftz.f32 %0, %1;" : "=f"(r) : "f"(x)); return r;
}
#define CP_ASYNC16(dst, src) \
    asm volatile("cp.async.cg.shared.global [%0], [%1], 16;" :: "r"(dst), "l"(src))
#define CP_COMMIT() asm volatile("cp.async.commit_group;" ::: "memory")
#define CP_WAIT(n)  asm volatile("cp.async.wait_group %0;" :: "n"(n) : "memory")

__device__ __forceinline__ void ldsm4(uint32_t* r, uint32_t addr) {
    asm volatile("ldmatrix.sync.aligned.m8n8.x4.shared.b16 {%0,%1,%2,%3}, [%4];"
                 : "=r"(r[0]), "=r"(r[1]), "=r"(r[2]), "=r"(r[3]) : "r"(addr));
}
__device__ __forceinline__ void mma_bf16(float* c, const uint32_t* a, const uint32_t* b) {
    asm volatile(
        "mma.sync.aligned.m16n8k16.row.col.f32.bf16.bf16.f32 "
        "{%0,%1,%2,%3}, {%4,%5,%6,%7}, {%8,%9}, {%0,%1,%2,%3};"
        : "+f"(c[0]), "+f"(c[1]), "+f"(c[2]), "+f"(c[3])
        : "r"(a[0]), "r"(a[1]), "r"(a[2]), "r"(a[3]), "r"(b[0]), "r"(b[1]));
}

// ---------------------------------------------------------------------------
// Kernel 1: L2-normalize -> bf16, pre-scaled by sqrt(C_EX2). One warp per row.
// ---------------------------------------------------------------------------
__global__ void norm_bf16_kernel(const float* __restrict__ emb_i,
                                 const float* __restrict__ emb_j) {
    int warp = (blockIdx.x * blockDim.x + threadIdx.x) >> 5;
    int lane = threadIdx.x & 31;
    if (warp >= LAYERS * TWON) return;
    int layer = warp >> 12;
    int row   = warp & (TWON - 1);

    const float* src = (row < N_)
        ? (emb_i + ((size_t)layer * N_ + row) * D_)
        : (emb_j + ((size_t)layer * N_ + (row - N_)) * D_);

    float4 v = ((const float4*)src)[lane];
    float s = v.x * v.x + v.y * v.y + v.z * v.z + v.w * v.w;
    #pragma unroll
    for (int o = 16; o > 0; o >>= 1) s += __shfl_xor_sync(0xffffffffu, s, o);

    float inv = SQC / fmaxf(sqrtf(s), EPS);
    uint2 u;
    u.x = (uint32_t)__bfloat16_as_ushort(__float2bfloat16(v.x * inv))
        | ((uint32_t)__bfloat16_as_ushort(__float2bfloat16(v.y * inv)) << 16);
    u.y = (uint32_t)__bfloat16_as_ushort(__float2bfloat16(v.z * inv))
        | ((uint32_t)__bfloat16_as_ushort(__float2bfloat16(v.w * inv)) << 16);
    ((uint2*)(g_zb + ((size_t)layer * TWON + row) * D_))[lane] = u;
}

// ---------------------------------------------------------------------------
// Kernel 2: symmetric fused Gram + exp.  Persistent: 132 CTAs x 16 tile-ops.
// Tile-op t -> (layer, i<=j).  Computes 128x128 sim tile once; row-sums of
// exp go to g_acc[l][i][j], col-sums (transpose contribution) to g_acc[l][j][i].
// Tile diagonal (rl==cl) is the self-sim on diag tiles and the positive pair
// on j==i+16 tiles.  Double-buffered A+B prefetch.
// ---------------------------------------------------------------------------
extern __shared__ char dsm[];

__device__ __forceinline__ void unrank(int t, int& layer, int& ib, int& jb) {
    layer = t / TOPSL;
    int rem = t - layer * TOPSL;
    int i = 0;
    while (rem >= NTILE - i) { rem -= NTILE - i; ++i; }
    ib = i; jb = i + rem;
}

__device__ __forceinline__ void load_pair(int layer, int ib, int jb,
                                          uint32_t base, int tid) {
    const __nv_bfloat16* Z = g_zb + (size_t)layer * TWON * D_;
    const __nv_bfloat16* Ai = Z + (size_t)ib * 128 * D_;
    const __nv_bfloat16* Bj = Z + (size_t)jb * 128 * D_;
    #pragma unroll
    for (int p = 0; p < 8; ++p) {
        int idx = p * 256 + tid;               // 2048 16B segs per tile
        int r = idx >> 4, sc = idx & 15;
        CP_ASYNC16(base + r * SROWB + sc * 16,
                   (const char*)(Ai + (size_t)r * D_) + sc * 16);
        CP_ASYNC16(base + TILEB + r * SROWB + sc * 16,
                   (const char*)(Bj + (size_t)r * D_) + sc * 16);
    }
}

__global__ void __launch_bounds__(256, 1) sim_sym_kernel() {
    __shared__ float red_r[2][128];
    __shared__ float red_c[4][128];

    int tid  = threadIdx.x;
    int wid  = tid >> 5;
    int lane = tid & 31;
    int warpRow = wid & 3;      // 4 slices of 32 rows
    int warpCol = wid >> 2;     // 2 slices of 64 cols

    uint32_t sb = (smem_u32(dsm) + 1023) & ~1023u;
    uint32_t buf[2] = { sb, sb + 2 * TILEB };

    uint32_t laneA = (uint32_t)((lane & 7) * SROWB + ((lane >> 3) & 1) * (8 * SROWB)
                                + ((lane >> 4) & 1) * 16);
    uint32_t laneB = (uint32_t)((lane & 7) * SROWB + ((lane >> 3) & 1) * 16
                                + ((lane >> 4) & 1) * (8 * SROWB));

    // Prologue: load tile-op 0
    int L0, I0, J0;
    unrank((int)blockIdx.x, L0, I0, J0);
    load_pair(L0, I0, J0, buf[0], tid);
    CP_COMMIT();

    int layer = L0, ib = I0, jb = J0;

    for (int n = 0; n < TOPC; ++n) {
        CP_WAIT(0);
        __syncthreads();            // buf[n&1] ready; red arrays free

        int nlayer = 0, nib = 0, njb = 0;
        if (n + 1 < TOPC) {
            unrank((int)blockIdx.x + (n + 1) * NCTA, nlayer, nib, njb);
            load_pair(nlayer, nib, njb, buf[(n + 1) & 1], tid);
            CP_COMMIT();
        }

        // ---- compute tile (layer, ib, jb) from buf[n&1] ----
        uint32_t aA = buf[n & 1] + (uint32_t)(warpRow * 32 * SROWB) + laneA;
        uint32_t bA = buf[n & 1] + TILEB + (uint32_t)(warpCol * 64 * SROWB) + laneB;

        float acc[2][8][4];
        #pragma unroll
        for (int mt = 0; mt < 2; ++mt)
            #pragma unroll
            for (int nt = 0; nt < 8; ++nt)
                #pragma unroll
                for (int ci = 0; ci < 4; ++ci) acc[mt][nt][ci] = 0.f;

        #pragma unroll
        for (int kt = 0; kt < 8; ++kt) {
            uint32_t aF0[4], aF1[4];
            ldsm4(aF0, aA + (uint32_t)(kt * 32));
            ldsm4(aF1, aA + (uint32_t)(16 * SROWB + kt * 32));
            #pragma unroll
            for (int np = 0; np < 4; ++np) {
                uint32_t t[4];
                ldsm4(t, bA + (uint32_t)(np * 16 * SROWB + kt * 32));
                mma_bf16(acc[0][2 * np],     aF0, &t[0]);
                mma_bf16(acc[0][2 * np + 1], aF0, &t[2]);
                mma_bf16(acc[1][2 * np],     aF1, &t[0]);
                mma_bf16(acc[1][2 * np + 1], aF1, &t[2]);
            }
        }

        // ---- epilogue: exp, row-sums, col-sums, diagonal captures ----
        bool isDiag = (ib == jb);
        bool isPos  = (jb == ib + (N_ / 128));   // j = i + 16

        float dsum[4] = {0.f, 0.f, 0.f, 0.f};
        float csum[16];
        #pragma unroll
        for (int x = 0; x < 16; ++x) csum[x] = 0.f;

        #pragma unroll
        for (int mt = 0; mt < 2; ++mt)
            #pragma unroll
            for (int nt = 0; nt < 8; ++nt)
                #pragma unroll
                for (int ci = 0; ci < 4; ++ci) {
                    float s = acc[mt][nt][ci];       // already C_EX2-scaled
                    float e = ex2f(s);
                    dsum[mt * 2 + (ci >> 1)] += e;
                    csum[nt * 2 + (ci & 1)] += e;
                    if (isDiag | isPos) {
                        int rl = warpRow * 32 + (lane >> 2) + mt * 16 + (ci >> 1) * 8;
                        int cl = warpCol * 64 + nt * 8 + (lane & 3) * 2 + (ci & 1);
                        if (rl == cl) {
                            if (isDiag) g_diag[layer * TWON + ib * 128 + rl] = s;
                            else        g_posv[layer * N_   + ib * 128 + rl] = s;
                        }
                    }
                }

        // row reduction: over lane&3
        #pragma unroll
        for (int ri = 0; ri < 4; ++ri) {
            #pragma unroll
            for (int o = 1; o <= 2; o <<= 1)
                dsum[ri] += __shfl_xor_sync(0xffffffffu, dsum[ri], o);
        }
        if ((lane & 3) == 0) {
            #pragma unroll
            for (int ri = 0; ri < 4; ++ri) {
                int rloc = warpRow * 32 + (ri >> 1) * 16 + (ri & 1) * 8 + (lane >> 2);
                red_r[warpCol][rloc] = dsum[ri];
            }
        }
        // col reduction: over lane>>2 (xor 4,8,16)
        #pragma unroll
        for (int x = 0; x < 16; ++x) {
            #pragma unroll
            for (int o = 4; o <= 16; o <<= 1)
                csum[x] += __shfl_xor_sync(0xffffffffu, csum[x], o);
        }
        if (lane < 4) {
            #pragma unroll
            for (int x = 0; x < 16; ++x) {
                int cl = warpCol * 64 + (x >> 1) * 8 + lane * 2 + (x & 1);
                red_c[warpRow][cl] = csum[x];
            }
        }
        __syncthreads();

        if (tid < 128) {
            float rs = red_r[0][tid] + red_r[1][tid];
            g_acc[(((size_t)layer * NTILE + ib) * NTILE + jb) * 128 + tid] = rs;
        } else if (!isDiag) {
            int c = tid - 128;
            float cs = red_c[0][c] + red_c[1][c] + red_c[2][c] + red_c[3][c];
            g_acc[(((size_t)layer * NTILE + jb) * NTILE + ib) * 128 + c] = cs;
        }

        layer = nlayer; ib = nib; jb = njb;
    }
}

// ---------------------------------------------------------------------------
// Kernel 3: per-row loss partial from the 32 exp-sum slots.
// ---------------------------------------------------------------------------
__global__ void lp_kernel() {
    int ridx = blockIdx.x * blockDim.x + threadIdx.x;   // [0, LAYERS*TWON)
    if (ridx >= LAYERS * TWON) return;
    int layer = ridx >> 12;
    int r     = ridx & (TWON - 1);
    int blk   = r >> 7;
    int rl    = r & 127;

    const float* slots = g_acc + (((size_t)layer * NTILE + blk) * NTILE) * 128 + rl;
    float d = 0.f;
    #pragma unroll
    for (int k = 0; k < NTILE; ++k) d += slots[k * 128];

    float denom = d - ex2f(g_diag[ridx]);                 // remove self term
    float posac = g_posv[layer * N_ + (r & (N_ - 1))];    // C*s_pos
    g_lp[ridx] = logf(denom) - posac * LN2F;
}

// ---------------------------------------------------------------------------
// Kernel 4: deterministic final reduction with joint_valid mask.
// ---------------------------------------------------------------------------
__global__ void finalize_kernel(const float* __restrict__ joint_valid,
                                float* __restrict__ out) {
    __shared__ float s1[256];
    __shared__ float s2[256];
    int tid = threadIdx.x;

    float total = 0.f;
    for (int idx = tid; idx < LAYERS * TWON; idx += 256) {
        int row = idx & (TWON - 1);
        total += g_lp[idx] * joint_valid[row & (N_ - 1)];
    }
    float an = 0.f;
    for (int idx = tid; idx < N_; idx += 256) an += joint_valid[idx];

    s1[tid] = total;
    s2[tid] = an;
    __syncthreads();
    for (int s = 128; s > 0; s >>= 1) {
        if (tid < s) { s1[tid] += s1[tid + s]; s2[tid] += s2[tid + s]; }
        __syncthreads();
    }
    if (tid == 0) out[0] = s1[0] / (2.0f * s2[0]);
}

// ---------------------------------------------------------------------------
extern "C" void kernel_launch(void* const* d_in, const int* in_sizes, int n_in,
                              void* d_out, int out_size) {
    const float* emb_i       = (const float*)d_in[0];
    const float* emb_j       = (const float*)d_in[1];
    const float* joint_valid = (const float*)d_in[2];
    float* out = (float*)d_out;
    (void)in_sizes; (void)n_in; (void)out_size;

    const int SIM_SMEM = 1024 + 4 * TILEB;   // 2 buffers x (A+B) = 140288 B
    cudaFuncSetAttribute(sim_sym_kernel, cudaFuncAttributeMaxDynamicSharedMemorySize, SIM_SMEM);

    norm_bf16_kernel<<<(LAYERS * TWON) / 8, 256>>>(emb_i, emb_j);
    sim_sym_kernel<<<NCTA, 256, SIM_SMEM>>>();
    lp_kernel<<<(LAYERS * TWON) / 256, 256>>>();
    finalize_kernel<<<1, 256>>>(joint_valid, out);
}

// round 9
// speedup vs baseline: 1.1255x; 1.0331x over previous
#include <cuda_runtime.h>
#include <cuda_bf16.h>
#include <math.h>
#include <stdint.h>

// Problem constants
#define LAYERS 4
#define D_     128
#define N_     2048
#define TWON   4096
#define INV_T  5.0f
#define EPS    1e-12f
#define C_EX2  7.21347520444481703076f   // (1/T) * log2(e)
#define SQC    2.68579079f               // sqrt(C_EX2); z stored as z*SQC => acc = C_EX2*s
#define LN2F   0.69314718056f            // INV_T / C_EX2

#define SROWB  272                       // smem row stride bytes (128 bf16 + 16B pad)
#define TILEB  (128 * SROWB)             // 34816
#define NTILE  32                        // 4096/128 blocks per layer
#define TOPSL  528                       // NTILE*(NTILE+1)/2 tile-ops per layer
#define NCTA   132                       // 2112 total tile-ops / 132 = 16 each
#define TOPC   16                        // tile-ops per CTA
#define RBLK   64                        // reduction blocks (16384 rows / 256)

// Scratch
__device__ __align__(256) __nv_bfloat16 g_zb[LAYERS * TWON * D_];
__device__ float g_acc[LAYERS * NTILE * NTILE * 128];  // [l][i][j][rl] exp-sums (2MB)
__device__ float g_diag[LAYERS * TWON];                // scaled diag acc (C*s_ii)
__device__ float g_posv[LAYERS * N_];                  // scaled pos acc (C*s_pos)
__device__ float g_part[RBLK];                         // per-block masked partials

// ---------------------------------------------------------------------------
__device__ __forceinline__ uint32_t smem_u32(const void* p) {
    uint32_t a;
    asm("{ .reg .u64 t; cvta.to.shared.u64 t, %1; cvt.u32.u64 %0, t; }" : "=r"(a) : "l"(p));
    return a;
}
__device__ __forceinline__ float ex2f(float x) {
    float r; asm("ex2.approx.ftz.f32 %0, %1;" : "=f"(r) : "f"(x)); return r;
}
#define CP_ASYNC16(dst, src) \
    asm volatile("cp.async.cg.shared.global [%0], [%1], 16;" :: "r"(dst), "l"(src))
#define CP_COMMIT() asm volatile("cp.async.commit_group;" ::: "memory")
#define CP_WAIT(n)  asm volatile("cp.async.wait_group %0;" :: "n"(n) : "memory")

__device__ __forceinline__ void ldsm4(uint32_t* r, uint32_t addr) {
    asm volatile("ldmatrix.sync.aligned.m8n8.x4.shared.b16 {%0,%1,%2,%3}, [%4];"
                 : "=r"(r[0]), "=r"(r[1]), "=r"(r[2]), "=r"(r[3]) : "r"(addr));
}
__device__ __forceinline__ void mma_bf16(float* c, const uint32_t* a, const uint32_t* b) {
    asm volatile(
        "mma.sync.aligned.m16n8k16.row.col.f32.bf16.bf16.f32 "
        "{%0,%1,%2,%3}, {%4,%5,%6,%7}, {%8,%9}, {%0,%1,%2,%3};"
        : "+f"(c[0]), "+f"(c[1]), "+f"(c[2]), "+f"(c[3])
        : "r"(a[0]), "r"(a[1]), "r"(a[2]), "r"(a[3]), "r"(b[0]), "r"(b[1]));
}

// ---------------------------------------------------------------------------
// Kernel 1: L2-normalize -> bf16, pre-scaled by sqrt(C_EX2). One warp per row.
// ---------------------------------------------------------------------------
__global__ void norm_bf16_kernel(const float* __restrict__ emb_i,
                                 const float* __restrict__ emb_j) {
    int warp = (blockIdx.x * blockDim.x + threadIdx.x) >> 5;
    int lane = threadIdx.x & 31;
    if (warp >= LAYERS * TWON) return;
    int layer = warp >> 12;
    int row   = warp & (TWON - 1);

    const float* src = (row < N_)
        ? (emb_i + ((size_t)layer * N_ + row) * D_)
        : (emb_j + ((size_t)layer * N_ + (row - N_)) * D_);

    float4 v = ((const float4*)src)[lane];
    float s = v.x * v.x + v.y * v.y + v.z * v.z + v.w * v.w;
    #pragma unroll
    for (int o = 16; o > 0; o >>= 1) s += __shfl_xor_sync(0xffffffffu, s, o);

    float inv = SQC / fmaxf(sqrtf(s), EPS);
    uint2 u;
    u.x = (uint32_t)__bfloat16_as_ushort(__float2bfloat16(v.x * inv))
        | ((uint32_t)__bfloat16_as_ushort(__float2bfloat16(v.y * inv)) << 16);
    u.y = (uint32_t)__bfloat16_as_ushort(__float2bfloat16(v.z * inv))
        | ((uint32_t)__bfloat16_as_ushort(__float2bfloat16(v.w * inv)) << 16);
    ((uint2*)(g_zb + ((size_t)layer * TWON + row) * D_))[lane] = u;
}

// ---------------------------------------------------------------------------
// Kernel 2: symmetric fused Gram + exp.  Persistent: 132 CTAs x 16 tile-ops.
// (Unchanged from R8 — passing at rel_err 5.7e-7.)
// ---------------------------------------------------------------------------
extern __shared__ char dsm[];

__device__ __forceinline__ void unrank(int t, int& layer, int& ib, int& jb) {
    layer = t / TOPSL;
    int rem = t - layer * TOPSL;
    int i = 0;
    while (rem >= NTILE - i) { rem -= NTILE - i; ++i; }
    ib = i; jb = i + rem;
}

__device__ __forceinline__ void load_pair(int layer, int ib, int jb,
                                          uint32_t base, int tid) {
    const __nv_bfloat16* Z = g_zb + (size_t)layer * TWON * D_;
    const __nv_bfloat16* Ai = Z + (size_t)ib * 128 * D_;
    const __nv_bfloat16* Bj = Z + (size_t)jb * 128 * D_;
    #pragma unroll
    for (int p = 0; p < 8; ++p) {
        int idx = p * 256 + tid;               // 2048 16B segs per tile
        int r = idx >> 4, sc = idx & 15;
        CP_ASYNC16(base + r * SROWB + sc * 16,
                   (const char*)(Ai + (size_t)r * D_) + sc * 16);
        CP_ASYNC16(base + TILEB + r * SROWB + sc * 16,
                   (const char*)(Bj + (size_t)r * D_) + sc * 16);
    }
}

__global__ void __launch_bounds__(256, 1) sim_sym_kernel() {
    __shared__ float red_r[2][128];
    __shared__ float red_c[4][128];

    int tid  = threadIdx.x;
    int wid  = tid >> 5;
    int lane = tid & 31;
    int warpRow = wid & 3;      // 4 slices of 32 rows
    int warpCol = wid >> 2;     // 2 slices of 64 cols

    uint32_t sb = (smem_u32(dsm) + 1023) & ~1023u;
    uint32_t buf[2] = { sb, sb + 2 * TILEB };

    uint32_t laneA = (uint32_t)((lane & 7) * SROWB + ((lane >> 3) & 1) * (8 * SROWB)
                                + ((lane >> 4) & 1) * 16);
    uint32_t laneB = (uint32_t)((lane & 7) * SROWB + ((lane >> 3) & 1) * 16
                                + ((lane >> 4) & 1) * (8 * SROWB));

    // Prologue: load tile-op 0
    int L0, I0, J0;
    unrank((int)blockIdx.x, L0, I0, J0);
    load_pair(L0, I0, J0, buf[0], tid);
    CP_COMMIT();

    int layer = L0, ib = I0, jb = J0;

    for (int n = 0; n < TOPC; ++n) {
        CP_WAIT(0);
        __syncthreads();            // buf[n&1] ready; red arrays free

        int nlayer = 0, nib = 0, njb = 0;
        if (n + 1 < TOPC) {
            unrank((int)blockIdx.x + (n + 1) * NCTA, nlayer, nib, njb);
            load_pair(nlayer, nib, njb, buf[(n + 1) & 1], tid);
            CP_COMMIT();
        }

        // ---- compute tile (layer, ib, jb) from buf[n&1] ----
        uint32_t aA = buf[n & 1] + (uint32_t)(warpRow * 32 * SROWB) + laneA;
        uint32_t bA = buf[n & 1] + TILEB + (uint32_t)(warpCol * 64 * SROWB) + laneB;

        float acc[2][8][4];
        #pragma unroll
        for (int mt = 0; mt < 2; ++mt)
            #pragma unroll
            for (int nt = 0; nt < 8; ++nt)
                #pragma unroll
                for (int ci = 0; ci < 4; ++ci) acc[mt][nt][ci] = 0.f;

        #pragma unroll
        for (int kt = 0; kt < 8; ++kt) {
            uint32_t aF0[4], aF1[4];
            ldsm4(aF0, aA + (uint32_t)(kt * 32));
            ldsm4(aF1, aA + (uint32_t)(16 * SROWB + kt * 32));
            #pragma unroll
            for (int np = 0; np < 4; ++np) {
                uint32_t t[4];
                ldsm4(t, bA + (uint32_t)(np * 16 * SROWB + kt * 32));
                mma_bf16(acc[0][2 * np],     aF0, &t[0]);
                mma_bf16(acc[0][2 * np + 1], aF0, &t[2]);
                mma_bf16(acc[1][2 * np],     aF1, &t[0]);
                mma_bf16(acc[1][2 * np + 1], aF1, &t[2]);
            }
        }

        // ---- epilogue: exp, row-sums, col-sums, diagonal captures ----
        bool isDiag = (ib == jb);
        bool isPos  = (jb == ib + (N_ / 128));   // j = i + 16

        float dsum[4] = {0.f, 0.f, 0.f, 0.f};
        float csum[16];
        #pragma unroll
        for (int x = 0; x < 16; ++x) csum[x] = 0.f;

        #pragma unroll
        for (int mt = 0; mt < 2; ++mt)
            #pragma unroll
            for (int nt = 0; nt < 8; ++nt)
                #pragma unroll
                for (int ci = 0; ci < 4; ++ci) {
                    float s = acc[mt][nt][ci];       // already C_EX2-scaled
                    float e = ex2f(s);
                    dsum[mt * 2 + (ci >> 1)] += e;
                    csum[nt * 2 + (ci & 1)] += e;
                    if (isDiag | isPos) {
                        int rl = warpRow * 32 + (lane >> 2) + mt * 16 + (ci >> 1) * 8;
                        int cl = warpCol * 64 + nt * 8 + (lane & 3) * 2 + (ci & 1);
                        if (rl == cl) {
                            if (isDiag) g_diag[layer * TWON + ib * 128 + rl] = s;
                            else        g_posv[layer * N_   + ib * 128 + rl] = s;
                        }
                    }
                }

        // row reduction: over lane&3
        #pragma unroll
        for (int ri = 0; ri < 4; ++ri) {
            #pragma unroll
            for (int o = 1; o <= 2; o <<= 1)
                dsum[ri] += __shfl_xor_sync(0xffffffffu, dsum[ri], o);
        }
        if ((lane & 3) == 0) {
            #pragma unroll
            for (int ri = 0; ri < 4; ++ri) {
                int rloc = warpRow * 32 + (ri >> 1) * 16 + (ri & 1) * 8 + (lane >> 2);
                red_r[warpCol][rloc] = dsum[ri];
            }
        }
        // col reduction: over lane>>2 (xor 4,8,16)
        #pragma unroll
        for (int x = 0; x < 16; ++x) {
            #pragma unroll
            for (int o = 4; o <= 16; o <<= 1)
                csum[x] += __shfl_xor_sync(0xffffffffu, csum[x], o);
        }
        if (lane < 4) {
            #pragma unroll
            for (int x = 0; x < 16; ++x) {
                int cl = warpCol * 64 + (x >> 1) * 8 + lane * 2 + (x & 1);
                red_c[warpRow][cl] = csum[x];
            }
        }
        __syncthreads();

        if (tid < 128) {
            float rs = red_r[0][tid] + red_r[1][tid];
            g_acc[(((size_t)layer * NTILE + ib) * NTILE + jb) * 128 + tid] = rs;
        } else if (!isDiag) {
            int c = tid - 128;
            float cs = red_c[0][c] + red_c[1][c] + red_c[2][c] + red_c[3][c];
            g_acc[(((size_t)layer * NTILE + jb) * NTILE + ib) * 128 + c] = cs;
        }

        layer = nlayer; ib = nib; jb = njb;
    }
}

// ---------------------------------------------------------------------------
// Kernel 3: lp + mask + per-block partial reduction.  64 blocks x 256 threads,
// one thread per row.  Deterministic smem tree reduce.
// ---------------------------------------------------------------------------
__global__ void lp_reduce_kernel(const float* __restrict__ joint_valid) {
    __shared__ float s1[256];
    int tid  = threadIdx.x;
    int ridx = blockIdx.x * 256 + tid;     // [0, LAYERS*TWON)
    int layer = ridx >> 12;
    int r     = ridx & (TWON - 1);
    int blk   = r >> 7;
    int rl    = r & 127;

    const float* slots = g_acc + (((size_t)layer * NTILE + blk) * NTILE) * 128 + rl;
    float d = 0.f;
    #pragma unroll
    for (int k = 0; k < NTILE; ++k) d += slots[k * 128];

    float denom = d - ex2f(g_diag[ridx]);                 // remove self term
    float posac = g_posv[layer * N_ + (r & (N_ - 1))];    // C*s_pos
    float lp = logf(denom) - posac * LN2F;

    s1[tid] = lp * joint_valid[r & (N_ - 1)];
    __syncthreads();
    #pragma unroll
    for (int s = 128; s > 0; s >>= 1) {
        if (tid < s) s1[tid] += s1[tid + s];
        __syncthreads();
    }
    if (tid == 0) g_part[blockIdx.x] = s1[0];
}

// ---------------------------------------------------------------------------
// Kernel 4: tiny final combine — 64 partials + mask sum.
// ---------------------------------------------------------------------------
__global__ void final_kernel(const float* __restrict__ joint_valid,
                             float* __restrict__ out) {
    __shared__ float s1[256];
    __shared__ float s2[256];
    int tid = threadIdx.x;

    float t = (tid < RBLK) ? g_part[tid] : 0.f;
    float an = 0.f;
    #pragma unroll
    for (int k = 0; k < N_ / 256; ++k) an += joint_valid[k * 256 + tid];

    s1[tid] = t;
    s2[tid] = an;
    __syncthreads();
    #pragma unroll
    for (int s = 128; s > 0; s >>= 1) {
        if (tid < s) { s1[tid] += s1[tid + s]; s2[tid] += s2[tid + s]; }
        __syncthreads();
    }
    if (tid == 0) out[0] = s1[0] / (2.0f * s2[0]);
}

// ---------------------------------------------------------------------------
extern "C" void kernel_launch(void* const* d_in, const int* in_sizes, int n_in,
                              void* d_out, int out_size) {
    const float* emb_i       = (const float*)d_in[0];
    const float* emb_j       = (const float*)d_in[1];
    const float* joint_valid = (const float*)d_in[2];
    float* out = (float*)d_out;
    (void)in_sizes; (void)n_in; (void)out_size;

    const int SIM_SMEM = 1024 + 4 * TILEB;   // 2 buffers x (A+B) = 140288 B
    cudaFuncSetAttribute(sim_sym_kernel, cudaFuncAttributeMaxDynamicSharedMemorySize, SIM_SMEM);

    norm_bf16_kernel<<<(LAYERS * TWON) / 8, 256>>>(emb_i, emb_j);
    sim_sym_kernel<<<NCTA, 256, SIM_SMEM>>>();
    lp_reduce_kernel<<<RBLK, 256>>>(joint_valid);
    final_kernel<<<1, 256>>>(joint_valid, out);
}

// round 10
// speedup vs baseline: 1.1590x; 1.0298x over previous
#include <cuda_runtime.h>
#include <cuda_bf16.h>
#include <math.h>
#include <stdint.h>

// Problem constants
#define LAYERS 4
#define D_     128
#define N_     2048
#define TWON   4096
#define INV_T  5.0f
#define EPS    1e-12f
#define C_EX2  7.21347520444481703076f   // (1/T) * log2(e)
#define SQC    2.68579079f               // sqrt(C_EX2); z stored as z*SQC => acc = C_EX2*s
#define LN2F   0.69314718056f            // INV_T / C_EX2

#define SROWB  272                       // smem row stride bytes (128 bf16 + 16B pad)
#define TILEB  (128 * SROWB)             // 34816
#define NTILE  32                        // 4096/128 blocks per layer
#define TOPSL  528                       // NTILE*(NTILE+1)/2 tile-ops per layer
#define NCTA   132                       // 2112 total tile-ops / 132 = 16 each
#define TOPC   16                        // tile-ops per CTA
#define RBLK   64                        // reduction blocks (16384 rows / 256)

// Scratch
__device__ __align__(256) __nv_bfloat16 g_zb[LAYERS * TWON * D_];
__device__ float g_acc[LAYERS * NTILE * NTILE * 128];  // [l][i][j][rl] exp-sums (2MB)
__device__ float g_diag[LAYERS * TWON];                // scaled diag acc (C*s_ii)
__device__ float g_posv[LAYERS * N_];                  // scaled pos acc (C*s_pos)
__device__ float g_part[RBLK];                         // per-block masked partials
__device__ unsigned int g_ctr;                         // last-block counter (self-resetting)

// ---------------------------------------------------------------------------
__device__ __forceinline__ uint32_t smem_u32(const void* p) {
    uint32_t a;
    asm("{ .reg .u64 t; cvta.to.shared.u64 t, %1; cvt.u32.u64 %0, t; }" : "=r"(a) : "l"(p));
    return a;
}
__device__ __forceinline__ float ex2f(float x) {
    float r; asm("ex2.approx.ftz.f32 %0, %1;" : "=f"(r) : "f"(x)); return r;
}
#define CP_ASYNC16(dst, src) \
    asm volatile("cp.async.cg.shared.global [%0], [%1], 16;" :: "r"(dst), "l"(src))
#define CP_COMMIT() asm volatile("cp.async.commit_group;" ::: "memory")
#define CP_WAIT(n)  asm volatile("cp.async.wait_group %0;" :: "n"(n) : "memory")

__device__ __forceinline__ void ldsm4(uint32_t* r, uint32_t addr) {
    asm volatile("ldmatrix.sync.aligned.m8n8.x4.shared.b16 {%0,%1,%2,%3}, [%4];"
                 : "=r"(r[0]), "=r"(r[1]), "=r"(r[2]), "=r"(r[3]) : "r"(addr));
}
__device__ __forceinline__ void mma_bf16(float* c, const uint32_t* a, const uint32_t* b) {
    asm volatile(
        "mma.sync.aligned.m16n8k16.row.col.f32.bf16.bf16.f32 "
        "{%0,%1,%2,%3}, {%4,%5,%6,%7}, {%8,%9}, {%0,%1,%2,%3};"
        : "+f"(c[0]), "+f"(c[1]), "+f"(c[2]), "+f"(c[3])
        : "r"(a[0]), "r"(a[1]), "r"(a[2]), "r"(a[3]), "r"(b[0]), "r"(b[1]));
}

// ---------------------------------------------------------------------------
// Kernel 1: L2-normalize -> bf16, pre-scaled by sqrt(C_EX2). One warp per row.
// ---------------------------------------------------------------------------
__global__ void norm_bf16_kernel(const float* __restrict__ emb_i,
                                 const float* __restrict__ emb_j) {
    int warp = (blockIdx.x * blockDim.x + threadIdx.x) >> 5;
    int lane = threadIdx.x & 31;
    if (warp >= LAYERS * TWON) return;
    int layer = warp >> 12;
    int row   = warp & (TWON - 1);

    const float* src = (row < N_)
        ? (emb_i + ((size_t)layer * N_ + row) * D_)
        : (emb_j + ((size_t)layer * N_ + (row - N_)) * D_);

    float4 v = ((const float4*)src)[lane];
    float s = v.x * v.x + v.y * v.y + v.z * v.z + v.w * v.w;
    #pragma unroll
    for (int o = 16; o > 0; o >>= 1) s += __shfl_xor_sync(0xffffffffu, s, o);

    float inv = SQC / fmaxf(sqrtf(s), EPS);
    uint2 u;
    u.x = (uint32_t)__bfloat16_as_ushort(__float2bfloat16(v.x * inv))
        | ((uint32_t)__bfloat16_as_ushort(__float2bfloat16(v.y * inv)) << 16);
    u.y = (uint32_t)__bfloat16_as_ushort(__float2bfloat16(v.z * inv))
        | ((uint32_t)__bfloat16_as_ushort(__float2bfloat16(v.w * inv)) << 16);
    ((uint2*)(g_zb + ((size_t)layer * TWON + row) * D_))[lane] = u;
}

// ---------------------------------------------------------------------------
// Kernel 2: symmetric fused Gram + exp.  Persistent: 132 CTAs x 16 tile-ops.
// NOW 512 threads (16 warps, 4/SMSP) — warp grid 4x4 (m_w=32, n_w=32).
// ---------------------------------------------------------------------------
extern __shared__ char dsm[];

__device__ __forceinline__ void unrank(int t, int& layer, int& ib, int& jb) {
    layer = t / TOPSL;
    int rem = t - layer * TOPSL;
    int i = 0;
    while (rem >= NTILE - i) { rem -= NTILE - i; ++i; }
    ib = i; jb = i + rem;
}

__device__ __forceinline__ void load_pair(int layer, int ib, int jb,
                                          uint32_t base, int tid) {
    const __nv_bfloat16* Z = g_zb + (size_t)layer * TWON * D_;
    const __nv_bfloat16* Ai = Z + (size_t)ib * 128 * D_;
    const __nv_bfloat16* Bj = Z + (size_t)jb * 128 * D_;
    #pragma unroll
    for (int p = 0; p < 4; ++p) {
        int idx = p * 512 + tid;               // 2048 16B segs per tile
        int r = idx >> 4, sc = idx & 15;
        CP_ASYNC16(base + r * SROWB + sc * 16,
                   (const char*)(Ai + (size_t)r * D_) + sc * 16);
        CP_ASYNC16(base + TILEB + r * SROWB + sc * 16,
                   (const char*)(Bj + (size_t)r * D_) + sc * 16);
    }
}

__global__ void __launch_bounds__(512, 1) sim_sym_kernel() {
    __shared__ float red_r[4][128];
    __shared__ float red_c[4][128];

    int tid  = threadIdx.x;
    int wid  = tid >> 5;
    int lane = tid & 31;
    int warpRow = wid & 3;      // 4 slices of 32 rows
    int warpCol = wid >> 2;     // 4 slices of 32 cols

    uint32_t sb = (smem_u32(dsm) + 1023) & ~1023u;
    uint32_t buf[2] = { sb, sb + 2 * TILEB };

    uint32_t laneA = (uint32_t)((lane & 7) * SROWB + ((lane >> 3) & 1) * (8 * SROWB)
                                + ((lane >> 4) & 1) * 16);
    uint32_t laneB = (uint32_t)((lane & 7) * SROWB + ((lane >> 3) & 1) * 16
                                + ((lane >> 4) & 1) * (8 * SROWB));

    int L0, I0, J0;
    unrank((int)blockIdx.x, L0, I0, J0);
    load_pair(L0, I0, J0, buf[0], tid);
    CP_COMMIT();

    int layer = L0, ib = I0, jb = J0;

    for (int n = 0; n < TOPC; ++n) {
        CP_WAIT(0);
        __syncthreads();            // buf[n&1] ready; red arrays free

        int nlayer = 0, nib = 0, njb = 0;
        if (n + 1 < TOPC) {
            unrank((int)blockIdx.x + (n + 1) * NCTA, nlayer, nib, njb);
            load_pair(nlayer, nib, njb, buf[(n + 1) & 1], tid);
            CP_COMMIT();
        }

        uint32_t aA = buf[n & 1] + (uint32_t)(warpRow * 32 * SROWB) + laneA;
        uint32_t bA = buf[n & 1] + TILEB + (uint32_t)(warpCol * 32 * SROWB) + laneB;

        float acc[2][4][4];
        #pragma unroll
        for (int mt = 0; mt < 2; ++mt)
            #pragma unroll
            for (int nt = 0; nt < 4; ++nt)
                #pragma unroll
                for (int ci = 0; ci < 4; ++ci) acc[mt][nt][ci] = 0.f;

        #pragma unroll
        for (int kt = 0; kt < 8; ++kt) {
            uint32_t aF0[4], aF1[4];
            ldsm4(aF0, aA + (uint32_t)(kt * 32));
            ldsm4(aF1, aA + (uint32_t)(16 * SROWB + kt * 32));
            #pragma unroll
            for (int np = 0; np < 2; ++np) {
                uint32_t t[4];
                ldsm4(t, bA + (uint32_t)(np * 16 * SROWB + kt * 32));
                mma_bf16(acc[0][2 * np],     aF0, &t[0]);
                mma_bf16(acc[0][2 * np + 1], aF0, &t[2]);
                mma_bf16(acc[1][2 * np],     aF1, &t[0]);
                mma_bf16(acc[1][2 * np + 1], aF1, &t[2]);
            }
        }

        // ---- epilogue: exp, row-sums, col-sums, diagonal captures ----
        bool isDiag = (ib == jb);
        bool isPos  = (jb == ib + (N_ / 128));

        float dsum[4] = {0.f, 0.f, 0.f, 0.f};
        float csum[8];
        #pragma unroll
        for (int x = 0; x < 8; ++x) csum[x] = 0.f;

        #pragma unroll
        for (int mt = 0; mt < 2; ++mt)
            #pragma unroll
            for (int nt = 0; nt < 4; ++nt)
                #pragma unroll
                for (int ci = 0; ci < 4; ++ci) {
                    float s = acc[mt][nt][ci];       // already C_EX2-scaled
                    float e = ex2f(s);
                    dsum[mt * 2 + (ci >> 1)] += e;
                    csum[nt * 2 + (ci & 1)] += e;
                    if (isDiag | isPos) {
                        int rl = warpRow * 32 + (lane >> 2) + mt * 16 + (ci >> 1) * 8;
                        int cl = warpCol * 32 + nt * 8 + (lane & 3) * 2 + (ci & 1);
                        if (rl == cl) {
                            if (isDiag) g_diag[layer * TWON + ib * 128 + rl] = s;
                            else        g_posv[layer * N_   + ib * 128 + rl] = s;
                        }
                    }
                }

        // row reduction: over lane&3
        #pragma unroll
        for (int ri = 0; ri < 4; ++ri) {
            #pragma unroll
            for (int o = 1; o <= 2; o <<= 1)
                dsum[ri] += __shfl_xor_sync(0xffffffffu, dsum[ri], o);
        }
        if ((lane & 3) == 0) {
            #pragma unroll
            for (int ri = 0; ri < 4; ++ri) {
                int rloc = warpRow * 32 + (ri >> 1) * 16 + (ri & 1) * 8 + (lane >> 2);
                red_r[warpCol][rloc] = dsum[ri];
            }
        }
        // col reduction: over lane>>2 (xor 4,8,16)
        #pragma unroll
        for (int x = 0; x < 8; ++x) {
            #pragma unroll
            for (int o = 4; o <= 16; o <<= 1)
                csum[x] += __shfl_xor_sync(0xffffffffu, csum[x], o);
        }
        if (lane < 4) {
            #pragma unroll
            for (int x = 0; x < 8; ++x) {
                int cl = warpCol * 32 + (x >> 1) * 8 + lane * 2 + (x & 1);
                red_c[warpRow][cl] = csum[x];
            }
        }
        __syncthreads();

        if (tid < 128) {
            float rs = red_r[0][tid] + red_r[1][tid] + red_r[2][tid] + red_r[3][tid];
            g_acc[(((size_t)layer * NTILE + ib) * NTILE + jb) * 128 + tid] = rs;
        } else if (tid < 256 && !isDiag) {
            int c = tid - 128;
            float cs = red_c[0][c] + red_c[1][c] + red_c[2][c] + red_c[3][c];
            g_acc[(((size_t)layer * NTILE + jb) * NTILE + ib) * 128 + c] = cs;
        }

        layer = nlayer; ib = nib; jb = njb;
    }
}

// ---------------------------------------------------------------------------
// Kernel 3: lp + mask + block partials + fused last-block final combine.
// 64 blocks x 256 threads, one thread per row. Counter self-resets for graphs.
// ---------------------------------------------------------------------------
__global__ void lp_reduce_kernel(const float* __restrict__ joint_valid,
                                 float* __restrict__ out) {
    __shared__ float s1[256];
    __shared__ unsigned int isLast;
    int tid  = threadIdx.x;
    int ridx = blockIdx.x * 256 + tid;     // [0, LAYERS*TWON)
    int layer = ridx >> 12;
    int r     = ridx & (TWON - 1);
    int blk   = r >> 7;
    int rl    = r & 127;

    const float* slots = g_acc + (((size_t)layer * NTILE + blk) * NTILE) * 128 + rl;
    float d = 0.f;
    #pragma unroll
    for (int k = 0; k < NTILE; ++k) d += slots[k * 128];

    float denom = d - ex2f(g_diag[ridx]);                 // remove self term
    float posac = g_posv[layer * N_ + (r & (N_ - 1))];    // C*s_pos
    float lp = logf(denom) - posac * LN2F;

    s1[tid] = lp * joint_valid[r & (N_ - 1)];
    __syncthreads();
    #pragma unroll
    for (int s = 128; s > 0; s >>= 1) {
        if (tid < s) s1[tid] += s1[tid + s];
        __syncthreads();
    }
    if (tid == 0) {
        g_part[blockIdx.x] = s1[0];
        __threadfence();
        unsigned int prev = atomicAdd(&g_ctr, 1u);
        isLast = (prev == RBLK - 1) ? 1u : 0u;
    }
    __syncthreads();

    if (isLast) {
        __threadfence();                  // see all g_part writes
        float t = (tid < RBLK) ? g_part[tid] : 0.f;
        float an = 0.f;
        #pragma unroll
        for (int k = 0; k < N_ / 256; ++k) an += joint_valid[k * 256 + tid];

        __shared__ float s2[256];
        s1[tid] = t;
        s2[tid] = an;
        __syncthreads();
        #pragma unroll
        for (int s = 128; s > 0; s >>= 1) {
            if (tid < s) { s1[tid] += s1[tid + s]; s2[tid] += s2[tid + s]; }
            __syncthreads();
        }
        if (tid == 0) {
            out[0] = s1[0] / (2.0f * s2[0]);
            g_ctr = 0u;                   // reset for next graph replay
        }
    }
}

// ---------------------------------------------------------------------------
extern "C" void kernel_launch(void* const* d_in, const int* in_sizes, int n_in,
                              void* d_out, int out_size) {
    const float* emb_i       = (const float*)d_in[0];
    const float* emb_j       = (const float*)d_in[1];
    const float* joint_valid = (const float*)d_in[2];
    float* out = (float*)d_out;
    (void)in_sizes; (void)n_in; (void)out_size;

    const int SIM_SMEM = 1024 + 4 * TILEB;   // 2 buffers x (A+B) = 140288 B
    cudaFuncSetAttribute(sim_sym_kernel, cudaFuncAttributeMaxDynamicSharedMemorySize, SIM_SMEM);

    norm_bf16_kernel<<<(LAYERS * TWON) / 8, 256>>>(emb_i, emb_j);
    sim_sym_kernel<<<NCTA, 512, SIM_SMEM>>>();
    lp_reduce_kernel<<<RBLK, 256>>>(joint_valid, out);
}

// round 11
// speedup vs baseline: 1.2530x; 1.0811x over previous
#include <cuda_runtime.h>
#include <cuda_bf16.h>
#include <math.h>
#include <stdint.h>

// Problem constants
#define LAYERS 4
#define D_     128
#define N_     2048
#define TWON   4096
#define INV_T  5.0f
#define EPS    1e-12f
#define C_EX2  7.21347520444481703076f   // (1/T) * log2(e)
#define SQC    2.68579079f               // sqrt(C_EX2); z stored as z*SQC => acc = C_EX2*s
#define LN2F   0.69314718056f            // INV_T / C_EX2

#define SROWB  272                       // smem row stride bytes (128 bf16 + 16B pad)
#define TILEB  (128 * SROWB)             // 34816
#define NTILE  32                        // 4096/128 blocks per layer
#define TOPSL  528                       // NTILE*(NTILE+1)/2 tile-ops per layer
#define TOTOPS (LAYERS * TOPSL)          // 2112
#define NCTA   148                       // all SMs; 40 CTAs do 15 ops, 108 do 14
#define RBLK   64                        // reduction blocks (16384 rows / 256)

// Scratch
__device__ __align__(256) __nv_bfloat16 g_zb[LAYERS * TWON * D_];
__device__ float g_acc[LAYERS * NTILE * NTILE * 128];  // [l][i][j][rl] exp-sums (2MB)
__device__ float g_diag[LAYERS * TWON];                // scaled diag acc (C*s_ii)
__device__ float g_posv[LAYERS * N_];                  // scaled pos acc (C*s_pos)
__device__ float g_part[RBLK];                         // per-block masked partials
__device__ unsigned int g_ctr;                         // last-block counter (self-resetting)

// ---------------------------------------------------------------------------
__device__ __forceinline__ uint32_t smem_u32(const void* p) {
    uint32_t a;
    asm("{ .reg .u64 t; cvta.to.shared.u64 t, %1; cvt.u32.u64 %0, t; }" : "=r"(a) : "l"(p));
    return a;
}
__device__ __forceinline__ float ex2f(float x) {
    float r; asm("ex2.approx.ftz.f32 %0, %1;" : "=f"(r) : "f"(x)); return r;
}
#define CP_ASYNC16(dst, src) \
    asm volatile("cp.async.cg.shared.global [%0], [%1], 16;" :: "r"(dst), "l"(src))
#define CP_COMMIT() asm volatile("cp.async.commit_group;" ::: "memory")
#define CP_WAIT(n)  asm volatile("cp.async.wait_group %0;" :: "n"(n) : "memory")

__device__ __forceinline__ void ldsm4(uint32_t* r, uint32_t addr) {
    asm volatile("ldmatrix.sync.aligned.m8n8.x4.shared.b16 {%0,%1,%2,%3}, [%4];"
                 : "=r"(r[0]), "=r"(r[1]), "=r"(r[2]), "=r"(r[3]) : "r"(addr));
}
__device__ __forceinline__ void mma_bf16(float* c, const uint32_t* a, const uint32_t* b) {
    asm volatile(
        "mma.sync.aligned.m16n8k16.row.col.f32.bf16.bf16.f32 "
        "{%0,%1,%2,%3}, {%4,%5,%6,%7}, {%8,%9}, {%0,%1,%2,%3};"
        : "+f"(c[0]), "+f"(c[1]), "+f"(c[2]), "+f"(c[3])
        : "r"(a[0]), "r"(a[1]), "r"(a[2]), "r"(a[3]), "r"(b[0]), "r"(b[1]));
}

// ---------------------------------------------------------------------------
// Kernel 1: L2-normalize -> bf16, pre-scaled by sqrt(C_EX2). One warp per row.
// ---------------------------------------------------------------------------
__global__ void norm_bf16_kernel(const float* __restrict__ emb_i,
                                 const float* __restrict__ emb_j) {
    int warp = (blockIdx.x * blockDim.x + threadIdx.x) >> 5;
    int lane = threadIdx.x & 31;
    if (warp >= LAYERS * TWON) return;
    int layer = warp >> 12;
    int row   = warp & (TWON - 1);

    const float* src = (row < N_)
        ? (emb_i + ((size_t)layer * N_ + row) * D_)
        : (emb_j + ((size_t)layer * N_ + (row - N_)) * D_);

    float4 v = ((const float4*)src)[lane];
    float s = v.x * v.x + v.y * v.y + v.z * v.z + v.w * v.w;
    #pragma unroll
    for (int o = 16; o > 0; o >>= 1) s += __shfl_xor_sync(0xffffffffu, s, o);

    float inv = SQC / fmaxf(sqrtf(s), EPS);
    uint2 u;
    u.x = (uint32_t)__bfloat16_as_ushort(__float2bfloat16(v.x * inv))
        | ((uint32_t)__bfloat16_as_ushort(__float2bfloat16(v.y * inv)) << 16);
    u.y = (uint32_t)__bfloat16_as_ushort(__float2bfloat16(v.z * inv))
        | ((uint32_t)__bfloat16_as_ushort(__float2bfloat16(v.w * inv)) << 16);
    ((uint2*)(g_zb + ((size_t)layer * TWON + row) * D_))[lane] = u;
}

// ---------------------------------------------------------------------------
// Kernel 2: symmetric fused Gram + exp.  Persistent, 148 CTAs, grid-stride over
// 2112 tile-ops.  512 threads (4x4 warp grid).  ONE barrier per tile-op:
// reductions go to phase-alternating smem arrays; flush of phase p happens
// after the next iteration's top barrier.
// ---------------------------------------------------------------------------
extern __shared__ char dsm[];

__device__ __forceinline__ void unrank(int t, int& layer, int& ib, int& jb) {
    layer = t / TOPSL;
    int rem = t - layer * TOPSL;
    int i = 0;
    while (rem >= NTILE - i) { rem -= NTILE - i; ++i; }
    ib = i; jb = i + rem;
}

__device__ __forceinline__ void load_pair(int layer, int ib, int jb,
                                          uint32_t base, int tid) {
    const __nv_bfloat16* Z = g_zb + (size_t)layer * TWON * D_;
    const __nv_bfloat16* Ai = Z + (size_t)ib * 128 * D_;
    const __nv_bfloat16* Bj = Z + (size_t)jb * 128 * D_;
    #pragma unroll
    for (int p = 0; p < 4; ++p) {
        int idx = p * 512 + tid;               // 2048 16B segs per tile
        int r = idx >> 4, sc = idx & 15;
        CP_ASYNC16(base + r * SROWB + sc * 16,
                   (const char*)(Ai + (size_t)r * D_) + sc * 16);
        CP_ASYNC16(base + TILEB + r * SROWB + sc * 16,
                   (const char*)(Bj + (size_t)r * D_) + sc * 16);
    }
}

__global__ void __launch_bounds__(512, 1) sim_sym_kernel() {
    __shared__ float red_r[2][4][128];
    __shared__ float red_c[2][4][128];

    int tid  = threadIdx.x;
    int wid  = tid >> 5;
    int lane = tid & 31;
    int warpRow = wid & 3;      // 4 slices of 32 rows
    int warpCol = wid >> 2;     // 4 slices of 32 cols

    uint32_t sb = (smem_u32(dsm) + 1023) & ~1023u;
    uint32_t buf[2] = { sb, sb + 2 * TILEB };

    uint32_t laneA = (uint32_t)((lane & 7) * SROWB + ((lane >> 3) & 1) * (8 * SROWB)
                                + ((lane >> 4) & 1) * 16);
    uint32_t laneB = (uint32_t)((lane & 7) * SROWB + ((lane >> 3) & 1) * 16
                                + ((lane >> 4) & 1) * (8 * SROWB));

    int t = (int)blockIdx.x;
    int layer, ib, jb;
    unrank(t, layer, ib, jb);
    load_pair(layer, ib, jb, buf[0], tid);
    CP_COMMIT();

    int ph = 0;
    int havePrev = 0;
    int pl = 0, pib = 0, pjb = 0;

    while (true) {
        CP_WAIT(0);
        __syncthreads();          // buf[ph] ready; all prior red writes visible

        int tn = t + NCTA;
        int more = (tn < TOTOPS);
        int nlayer = 0, nib = 0, njb = 0;
        if (more) {
            unrank(tn, nlayer, nib, njb);
            load_pair(nlayer, nib, njb, buf[ph ^ 1], tid);
            CP_COMMIT();
        }

        // ---- flush previous tile-op's reductions (phase ph^1) ----
        if (havePrev) {
            if (tid < 128) {
                float rs = red_r[ph ^ 1][0][tid] + red_r[ph ^ 1][1][tid]
                         + red_r[ph ^ 1][2][tid] + red_r[ph ^ 1][3][tid];
                g_acc[(((size_t)pl * NTILE + pib) * NTILE + pjb) * 128 + tid] = rs;
            } else if (tid < 256 && pib != pjb) {
                int c = tid - 128;
                float cs = red_c[ph ^ 1][0][c] + red_c[ph ^ 1][1][c]
                         + red_c[ph ^ 1][2][c] + red_c[ph ^ 1][3][c];
                g_acc[(((size_t)pl * NTILE + pjb) * NTILE + pib) * 128 + c] = cs;
            }
        }

        // ---- compute tile (layer, ib, jb) from buf[ph] ----
        uint32_t aA = buf[ph] + (uint32_t)(warpRow * 32 * SROWB) + laneA;
        uint32_t bA = buf[ph] + TILEB + (uint32_t)(warpCol * 32 * SROWB) + laneB;

        float acc[2][4][4];
        #pragma unroll
        for (int mt = 0; mt < 2; ++mt)
            #pragma unroll
            for (int nt = 0; nt < 4; ++nt)
                #pragma unroll
                for (int ci = 0; ci < 4; ++ci) acc[mt][nt][ci] = 0.f;

        #pragma unroll
        for (int kt = 0; kt < 8; ++kt) {
            uint32_t aF0[4], aF1[4];
            ldsm4(aF0, aA + (uint32_t)(kt * 32));
            ldsm4(aF1, aA + (uint32_t)(16 * SROWB + kt * 32));
            #pragma unroll
            for (int np = 0; np < 2; ++np) {
                uint32_t tt[4];
                ldsm4(tt, bA + (uint32_t)(np * 16 * SROWB + kt * 32));
                mma_bf16(acc[0][2 * np],     aF0, &tt[0]);
                mma_bf16(acc[0][2 * np + 1], aF0, &tt[2]);
                mma_bf16(acc[1][2 * np],     aF1, &tt[0]);
                mma_bf16(acc[1][2 * np + 1], aF1, &tt[2]);
            }
        }

        // ---- epilogue: exp, row-sums, col-sums, diagonal captures ----
        bool isDiag = (ib == jb);
        bool isPos  = (jb == ib + (N_ / 128));

        float dsum[4] = {0.f, 0.f, 0.f, 0.f};
        float csum[8];
        #pragma unroll
        for (int x = 0; x < 8; ++x) csum[x] = 0.f;

        #pragma unroll
        for (int mt = 0; mt < 2; ++mt)
            #pragma unroll
            for (int nt = 0; nt < 4; ++nt)
                #pragma unroll
                for (int ci = 0; ci < 4; ++ci) {
                    float s = acc[mt][nt][ci];       // already C_EX2-scaled
                    float e = ex2f(s);
                    dsum[mt * 2 + (ci >> 1)] += e;
                    csum[nt * 2 + (ci & 1)] += e;
                    if (isDiag | isPos) {
                        int rl = warpRow * 32 + (lane >> 2) + mt * 16 + (ci >> 1) * 8;
                        int cl = warpCol * 32 + nt * 8 + (lane & 3) * 2 + (ci & 1);
                        if (rl == cl) {
                            if (isDiag) g_diag[layer * TWON + ib * 128 + rl] = s;
                            else        g_posv[layer * N_   + ib * 128 + rl] = s;
                        }
                    }
                }

        // row reduction: over lane&3
        #pragma unroll
        for (int ri = 0; ri < 4; ++ri) {
            #pragma unroll
            for (int o = 1; o <= 2; o <<= 1)
                dsum[ri] += __shfl_xor_sync(0xffffffffu, dsum[ri], o);
        }
        if ((lane & 3) == 0) {
            #pragma unroll
            for (int ri = 0; ri < 4; ++ri) {
                int rloc = warpRow * 32 + (ri >> 1) * 16 + (ri & 1) * 8 + (lane >> 2);
                red_r[ph][warpCol][rloc] = dsum[ri];
            }
        }
        // col reduction: over lane>>2 (xor 4,8,16)
        #pragma unroll
        for (int x = 0; x < 8; ++x) {
            #pragma unroll
            for (int o = 4; o <= 16; o <<= 1)
                csum[x] += __shfl_xor_sync(0xffffffffu, csum[x], o);
        }
        if (lane < 4) {
            #pragma unroll
            for (int x = 0; x < 8; ++x) {
                int cl = warpCol * 32 + (x >> 1) * 8 + lane * 2 + (x & 1);
                red_c[ph][warpRow][cl] = csum[x];
            }
        }
        // NO trailing barrier — next iteration's top barrier orders the flush.

        pl = layer; pib = ib; pjb = jb; havePrev = 1;
        if (!more) break;
        layer = nlayer; ib = nib; jb = njb;
        ph ^= 1;
        t = tn;
    }

    // final flush
    __syncthreads();
    if (tid < 128) {
        float rs = red_r[ph][0][tid] + red_r[ph][1][tid]
                 + red_r[ph][2][tid] + red_r[ph][3][tid];
        g_acc[(((size_t)pl * NTILE + pib) * NTILE + pjb) * 128 + tid] = rs;
    } else if (tid < 256 && pib != pjb) {
        int c = tid - 128;
        float cs = red_c[ph][0][c] + red_c[ph][1][c]
                 + red_c[ph][2][c] + red_c[ph][3][c];
        g_acc[(((size_t)pl * NTILE + pjb) * NTILE + pib) * 128 + c] = cs;
    }
}

// ---------------------------------------------------------------------------
// Kernel 3: lp + mask + block partials + fused last-block final combine.
// ---------------------------------------------------------------------------
__global__ void lp_reduce_kernel(const float* __restrict__ joint_valid,
                                 float* __restrict__ out) {
    __shared__ float s1[256];
    __shared__ unsigned int isLast;
    int tid  = threadIdx.x;
    int ridx = blockIdx.x * 256 + tid;     // [0, LAYERS*TWON)
    int layer = ridx >> 12;
    int r     = ridx & (TWON - 1);
    int blk   = r >> 7;
    int rl    = r & 127;

    const float* slots = g_acc + (((size_t)layer * NTILE + blk) * NTILE) * 128 + rl;
    float d = 0.f;
    #pragma unroll
    for (int k = 0; k < NTILE; ++k) d += slots[k * 128];

    float denom = d - ex2f(g_diag[ridx]);                 // remove self term
    float posac = g_posv[layer * N_ + (r & (N_ - 1))];    // C*s_pos
    float lp = logf(denom) - posac * LN2F;

    s1[tid] = lp * joint_valid[r & (N_ - 1)];
    __syncthreads();
    #pragma unroll
    for (int s = 128; s > 0; s >>= 1) {
        if (tid < s) s1[tid] += s1[tid + s];
        __syncthreads();
    }
    if (tid == 0) {
        g_part[blockIdx.x] = s1[0];
        __threadfence();
        unsigned int prev = atomicAdd(&g_ctr, 1u);
        isLast = (prev == RBLK - 1) ? 1u : 0u;
    }
    __syncthreads();

    if (isLast) {
        __threadfence();                  // see all g_part writes
        float tpart = (tid < RBLK) ? g_part[tid] : 0.f;
        float an = 0.f;
        #pragma unroll
        for (int k = 0; k < N_ / 256; ++k) an += joint_valid[k * 256 + tid];

        __shared__ float s2[256];
        s1[tid] = tpart;
        s2[tid] = an;
        __syncthreads();
        #pragma unroll
        for (int s = 128; s > 0; s >>= 1) {
            if (tid < s) { s1[tid] += s1[tid + s]; s2[tid] += s2[tid + s]; }
            __syncthreads();
        }
        if (tid == 0) {
            out[0] = s1[0] / (2.0f * s2[0]);
            g_ctr = 0u;                   // reset for next graph replay
        }
    }
}

// ---------------------------------------------------------------------------
extern "C" void kernel_launch(void* const* d_in, const int* in_sizes, int n_in,
                              void* d_out, int out_size) {
    const float* emb_i       = (const float*)d_in[0];
    const float* emb_j       = (const float*)d_in[1];
    const float* joint_valid = (const float*)d_in[2];
    float* out = (float*)d_out;
    (void)in_sizes; (void)n_in; (void)out_size;

    const int SIM_SMEM = 1024 + 4 * TILEB;   // 2 buffers x (A+B) = 140288 B
    cudaFuncSetAttribute(sim_sym_kernel, cudaFuncAttributeMaxDynamicSharedMemorySize, SIM_SMEM);

    norm_bf16_kernel<<<(LAYERS * TWON) / 8, 256>>>(emb_i, emb_j);
    sim_sym_kernel<<<NCTA, 512, SIM_SMEM>>>();
    lp_reduce_kernel<<<RBLK, 256>>>(joint_valid, out);
}

// round 12
// speedup vs baseline: 1.4793x; 1.1806x over previous
#include <cuda_runtime.h>
#include <cuda_bf16.h>
#include <math.h>
#include <stdint.h>

// Problem constants
#define LAYERS 4
#define D_     128
#define N_     2048
#define TWON   4096
#define INV_T  5.0f
#define EPS    1e-12f
#define C_EX2  7.21347520444481703076f   // (1/T) * log2(e)
#define SQC    2.68579079f               // sqrt(C_EX2); z stored as z*SQC => acc = C_EX2*s
#define LN2F   0.69314718056f            // INV_T / C_EX2

#define SROWB  272                       // smem row stride bytes (128 bf16 + 16B pad)
#define TILEB  (128 * SROWB)             // 34816
#define NTILE  32                        // 4096/128 blocks per layer
#define TOPSL  528                       // NTILE*(NTILE+1)/2 tile-ops per layer
#define TOTOPS (LAYERS * TOPSL)          // 2112
#define NCTA   296                       // 2 CTAs per SM
#define RBLK   64                        // reduction blocks (16384 rows / 256)

// Scratch
__device__ __align__(256) __nv_bfloat16 g_zb[LAYERS * TWON * D_];
__device__ float g_acc[LAYERS * NTILE * NTILE * 128];  // [l][i][j][rl] exp-sums (2MB)
__device__ float g_diag[LAYERS * TWON];                // scaled diag acc (C*s_ii)
__device__ float g_posv[LAYERS * N_];                  // scaled pos acc (C*s_pos)
__device__ float g_part[RBLK];                         // per-block masked partials
__device__ unsigned int g_ctr;                         // last-block counter (self-resetting)

// ---------------------------------------------------------------------------
__device__ __forceinline__ uint32_t smem_u32(const void* p) {
    uint32_t a;
    asm("{ .reg .u64 t; cvta.to.shared.u64 t, %1; cvt.u32.u64 %0, t; }" : "=r"(a) : "l"(p));
    return a;
}
__device__ __forceinline__ float ex2f(float x) {
    float r; asm("ex2.approx.ftz.f32 %0, %1;" : "=f"(r) : "f"(x)); return r;
}
#define CP_ASYNC16(dst, src) \
    asm volatile("cp.async.cg.shared.global [%0], [%1], 16;" :: "r"(dst), "l"(src))
#define CP_COMMIT() asm volatile("cp.async.commit_group;" ::: "memory")
#define CP_WAIT(n)  asm volatile("cp.async.wait_group %0;" :: "n"(n) : "memory")

__device__ __forceinline__ void ldsm4(uint32_t* r, uint32_t addr) {
    asm volatile("ldmatrix.sync.aligned.m8n8.x4.shared.b16 {%0,%1,%2,%3}, [%4];"
                 : "=r"(r[0]), "=r"(r[1]), "=r"(r[2]), "=r"(r[3]) : "r"(addr));
}
__device__ __forceinline__ void mma_bf16(float* c, const uint32_t* a, const uint32_t* b) {
    asm volatile(
        "mma.sync.aligned.m16n8k16.row.col.f32.bf16.bf16.f32 "
        "{%0,%1,%2,%3}, {%4,%5,%6,%7}, {%8,%9}, {%0,%1,%2,%3};"
        : "+f"(c[0]), "+f"(c[1]), "+f"(c[2]), "+f"(c[3])
        : "r"(a[0]), "r"(a[1]), "r"(a[2]), "r"(a[3]), "r"(b[0]), "r"(b[1]));
}

// ---------------------------------------------------------------------------
// Kernel 1: L2-normalize -> bf16, pre-scaled by sqrt(C_EX2). One warp per row.
// ---------------------------------------------------------------------------
__global__ void norm_bf16_kernel(const float* __restrict__ emb_i,
                                 const float* __restrict__ emb_j) {
    int warp = (blockIdx.x * blockDim.x + threadIdx.x) >> 5;
    int lane = threadIdx.x & 31;
    if (warp >= LAYERS * TWON) return;
    int layer = warp >> 12;
    int row   = warp & (TWON - 1);

    const float* src = (row < N_)
        ? (emb_i + ((size_t)layer * N_ + row) * D_)
        : (emb_j + ((size_t)layer * N_ + (row - N_)) * D_);

    float4 v = ((const float4*)src)[lane];
    float s = v.x * v.x + v.y * v.y + v.z * v.z + v.w * v.w;
    #pragma unroll
    for (int o = 16; o > 0; o >>= 1) s += __shfl_xor_sync(0xffffffffu, s, o);

    float inv = SQC * rsqrtf(fmaxf(s, EPS * EPS));
    uint2 u;
    u.x = (uint32_t)__bfloat16_as_ushort(__float2bfloat16(v.x * inv))
        | ((uint32_t)__bfloat16_as_ushort(__float2bfloat16(v.y * inv)) << 16);
    u.y = (uint32_t)__bfloat16_as_ushort(__float2bfloat16(v.z * inv))
        | ((uint32_t)__bfloat16_as_ushort(__float2bfloat16(v.w * inv)) << 16);
    ((uint2*)(g_zb + ((size_t)layer * TWON + row) * D_))[lane] = u;
}

// ---------------------------------------------------------------------------
// Kernel 2: symmetric fused Gram + exp.  296 CTAs x 256 threads, 2 CTAs/SM.
// Single-buffered A+B pair; cross-CTA interleaving hides load latency,
// epilogue and barriers (tensor pipe stays fed by the partner CTA).
// Warp grid 4x2: warpRow=wid&3 (32 rows), warpCol=wid>>2 (64 cols).
// ---------------------------------------------------------------------------
extern __shared__ char dsm[];

__device__ __forceinline__ void unrank(int t, int& layer, int& ib, int& jb) {
    layer = t / TOPSL;
    int rem = t - layer * TOPSL;
    int i = 0;
    while (rem >= NTILE - i) { rem -= NTILE - i; ++i; }
    ib = i; jb = i + rem;
}

__device__ __forceinline__ void load_pair(int layer, int ib, int jb,
                                          uint32_t base, int tid) {
    const __nv_bfloat16* Z = g_zb + (size_t)layer * TWON * D_;
    const __nv_bfloat16* Ai = Z + (size_t)ib * 128 * D_;
    const __nv_bfloat16* Bj = Z + (size_t)jb * 128 * D_;
    #pragma unroll
    for (int p = 0; p < 8; ++p) {
        int idx = p * 256 + tid;               // 2048 16B segs per tile
        int r = idx >> 4, sc = idx & 15;
        CP_ASYNC16(base + r * SROWB + sc * 16,
                   (const char*)(Ai + (size_t)r * D_) + sc * 16);
        CP_ASYNC16(base + TILEB + r * SROWB + sc * 16,
                   (const char*)(Bj + (size_t)r * D_) + sc * 16);
    }
}

__global__ void __launch_bounds__(256, 2) sim_sym_kernel() {
    __shared__ float red_r[2][128];
    __shared__ float red_c[4][128];

    int tid  = threadIdx.x;
    int wid  = tid >> 5;
    int lane = tid & 31;
    int warpRow = wid & 3;      // 4 slices of 32 rows
    int warpCol = wid >> 2;     // 2 slices of 64 cols

    uint32_t sb = (smem_u32(dsm) + 1023) & ~1023u;
    uint32_t buf = sb;

    uint32_t laneA = (uint32_t)((lane & 7) * SROWB + ((lane >> 3) & 1) * (8 * SROWB)
                                + ((lane >> 4) & 1) * 16);
    uint32_t laneB = (uint32_t)((lane & 7) * SROWB + ((lane >> 3) & 1) * 16
                                + ((lane >> 4) & 1) * (8 * SROWB));

    for (int t = (int)blockIdx.x; t < TOTOPS; t += NCTA) {
        int layer, ib, jb;
        unrank(t, layer, ib, jb);

        load_pair(layer, ib, jb, buf, tid);
        CP_COMMIT();
        CP_WAIT(0);
        __syncthreads();            // buf ready; red arrays free (prior flush done)

        uint32_t aA = buf + (uint32_t)(warpRow * 32 * SROWB) + laneA;
        uint32_t bA = buf + TILEB + (uint32_t)(warpCol * 64 * SROWB) + laneB;

        float acc[2][8][4];
        #pragma unroll
        for (int mt = 0; mt < 2; ++mt)
            #pragma unroll
            for (int nt = 0; nt < 8; ++nt)
                #pragma unroll
                for (int ci = 0; ci < 4; ++ci) acc[mt][nt][ci] = 0.f;

        #pragma unroll
        for (int kt = 0; kt < 8; ++kt) {
            uint32_t aF0[4], aF1[4];
            ldsm4(aF0, aA + (uint32_t)(kt * 32));
            ldsm4(aF1, aA + (uint32_t)(16 * SROWB + kt * 32));
            #pragma unroll
            for (int np = 0; np < 4; ++np) {
                uint32_t tt[4];
                ldsm4(tt, bA + (uint32_t)(np * 16 * SROWB + kt * 32));
                mma_bf16(acc[0][2 * np],     aF0, &tt[0]);
                mma_bf16(acc[0][2 * np + 1], aF0, &tt[2]);
                mma_bf16(acc[1][2 * np],     aF1, &tt[0]);
                mma_bf16(acc[1][2 * np + 1], aF1, &tt[2]);
            }
        }

        // ---- epilogue: exp, row-sums, col-sums, diagonal captures ----
        bool isDiag = (ib == jb);
        bool isPos  = (jb == ib + (N_ / 128));

        float dsum[4] = {0.f, 0.f, 0.f, 0.f};
        float csum[16];
        #pragma unroll
        for (int x = 0; x < 16; ++x) csum[x] = 0.f;

        #pragma unroll
        for (int mt = 0; mt < 2; ++mt)
            #pragma unroll
            for (int nt = 0; nt < 8; ++nt)
                #pragma unroll
                for (int ci = 0; ci < 4; ++ci) {
                    float s = acc[mt][nt][ci];       // already C_EX2-scaled
                    float e = ex2f(s);
                    dsum[mt * 2 + (ci >> 1)] += e;
                    csum[nt * 2 + (ci & 1)] += e;
                    if (isDiag | isPos) {
                        int rl = warpRow * 32 + (lane >> 2) + mt * 16 + (ci >> 1) * 8;
                        int cl = warpCol * 64 + nt * 8 + (lane & 3) * 2 + (ci & 1);
                        if (rl == cl) {
                            if (isDiag) g_diag[layer * TWON + ib * 128 + rl] = s;
                            else        g_posv[layer * N_   + ib * 128 + rl] = s;
                        }
                    }
                }

        // row reduction: over lane&3
        #pragma unroll
        for (int ri = 0; ri < 4; ++ri) {
            #pragma unroll
            for (int o = 1; o <= 2; o <<= 1)
                dsum[ri] += __shfl_xor_sync(0xffffffffu, dsum[ri], o);
        }
        if ((lane & 3) == 0) {
            #pragma unroll
            for (int ri = 0; ri < 4; ++ri) {
                int rloc = warpRow * 32 + (ri >> 1) * 16 + (ri & 1) * 8 + (lane >> 2);
                red_r[warpCol][rloc] = dsum[ri];
            }
        }
        // col reduction: over lane>>2 (xor 4,8,16)
        #pragma unroll
        for (int x = 0; x < 16; ++x) {
            #pragma unroll
            for (int o = 4; o <= 16; o <<= 1)
                csum[x] += __shfl_xor_sync(0xffffffffu, csum[x], o);
        }
        if (lane < 4) {
            #pragma unroll
            for (int x = 0; x < 16; ++x) {
                int cl = warpCol * 64 + (x >> 1) * 8 + lane * 2 + (x & 1);
                red_c[warpRow][cl] = csum[x];
            }
        }
        __syncthreads();            // red complete; buf reads complete

        if (tid < 128) {
            float rs = red_r[0][tid] + red_r[1][tid];
            g_acc[(((size_t)layer * NTILE + ib) * NTILE + jb) * 128 + tid] = rs;
        } else if (!isDiag) {
            int c = tid - 128;
            float cs = red_c[0][c] + red_c[1][c] + red_c[2][c] + red_c[3][c];
            g_acc[(((size_t)layer * NTILE + jb) * NTILE + ib) * 128 + c] = cs;
        }
        // next iteration's top barrier orders flush before red rewrite
    }
}

// ---------------------------------------------------------------------------
// Kernel 3: lp + mask + block partials + fused last-block final combine.
// ---------------------------------------------------------------------------
__global__ void lp_reduce_kernel(const float* __restrict__ joint_valid,
                                 float* __restrict__ out) {
    __shared__ float s1[256];
    __shared__ unsigned int isLast;
    int tid  = threadIdx.x;
    int ridx = blockIdx.x * 256 + tid;     // [0, LAYERS*TWON)
    int layer = ridx >> 12;
    int r     = ridx & (TWON - 1);
    int blk   = r >> 7;
    int rl    = r & 127;

    const float* slots = g_acc + (((size_t)layer * NTILE + blk) * NTILE) * 128 + rl;
    float d = 0.f;
    #pragma unroll
    for (int k = 0; k < NTILE; ++k) d += slots[k * 128];

    float denom = d - ex2f(g_diag[ridx]);                 // remove self term
    float posac = g_posv[layer * N_ + (r & (N_ - 1))];    // C*s_pos
    float lp = logf(denom) - posac * LN2F;

    s1[tid] = lp * joint_valid[r & (N_ - 1)];
    __syncthreads();
    #pragma unroll
    for (int s = 128; s > 0; s >>= 1) {
        if (tid < s) s1[tid] += s1[tid + s];
        __syncthreads();
    }
    if (tid == 0) {
        g_part[blockIdx.x] = s1[0];
        __threadfence();
        unsigned int prev = atomicAdd(&g_ctr, 1u);
        isLast = (prev == RBLK - 1) ? 1u : 0u;
    }
    __syncthreads();

    if (isLast) {
        __threadfence();                  // see all g_part writes
        float tpart = (tid < RBLK) ? g_part[tid] : 0.f;
        float an = 0.f;
        #pragma unroll
        for (int k = 0; k < N_ / 256; ++k) an += joint_valid[k * 256 + tid];

        __shared__ float s2[256];
        s1[tid] = tpart;
        s2[tid] = an;
        __syncthreads();
        #pragma unroll
        for (int s = 128; s > 0; s >>= 1) {
            if (tid < s) { s1[tid] += s1[tid + s]; s2[tid] += s2[tid + s]; }
            __syncthreads();
        }
        if (tid == 0) {
            out[0] = s1[0] / (2.0f * s2[0]);
            g_ctr = 0u;                   // reset for next graph replay
        }
    }
}

// ---------------------------------------------------------------------------
extern "C" void kernel_launch(void* const* d_in, const int* in_sizes, int n_in,
                              void* d_out, int out_size) {
    const float* emb_i       = (const float*)d_in[0];
    const float* emb_j       = (const float*)d_in[1];
    const float* joint_valid = (const float*)d_in[2];
    float* out = (float*)d_out;
    (void)in_sizes; (void)n_in; (void)out_size;

    const int SIM_SMEM = 1024 + 2 * TILEB;   // one A+B pair = 70656 B
    cudaFuncSetAttribute(sim_sym_kernel, cudaFuncAttributeMaxDynamicSharedMemorySize, SIM_SMEM);

    norm_bf16_kernel<<<(LAYERS * TWON) / 8, 256>>>(emb_i, emb_j);
    sim_sym_kernel<<<NCTA, 256, SIM_SMEM>>>();
    lp_reduce_kernel<<<RBLK, 256>>>(joint_valid, out);
}

// round 13
// speedup vs baseline: 1.5313x; 1.0351x over previous
#include <cuda_runtime.h>
#include <cuda_bf16.h>
#include <math.h>
#include <stdint.h>

// Problem constants
#define LAYERS 4
#define D_     128
#define N_     2048
#define TWON   4096
#define INV_T  5.0f
#define EPS    1e-12f
#define C_EX2  7.21347520444481703076f   // (1/T) * log2(e)
#define SQC    2.68579079f               // sqrt(C_EX2); z stored as z*SQC => acc = C_EX2*s
#define LN2F   0.69314718056f            // INV_T / C_EX2

#define SROWB  272                       // smem row stride bytes (128 bf16 + 16B pad)
#define TILEB  (128 * SROWB)             // 34816
#define NTILE  32                        // 4096/128 blocks per layer
#define TOPSL  528                       // NTILE*(NTILE+1)/2 tile-ops per layer
#define TOTOPS (LAYERS * TOPSL)          // 2112
#define NCTA   296                       // 2 CTAs per SM
#define RBLK   64                        // reduction blocks (16384 rows / 256)

// Scratch
__device__ __align__(256) __nv_bfloat16 g_zb[LAYERS * TWON * D_];
__device__ float g_acc[LAYERS * NTILE * NTILE * 128];  // [l][i][j][rl] exp-sums (2MB)
__device__ float g_diag[LAYERS * TWON];                // scaled diag acc (C*s_ii)
__device__ float g_posv[LAYERS * N_];                  // scaled pos acc (C*s_pos)
__device__ float g_part[RBLK];                         // per-block masked partials
__device__ unsigned int g_ctr;                         // last-block counter (self-resetting)
__device__ unsigned int g_tick = NCTA;                 // work-stealing ticket (reset by lp_reduce)

// ---------------------------------------------------------------------------
__device__ __forceinline__ uint32_t smem_u32(const void* p) {
    uint32_t a;
    asm("{ .reg .u64 t; cvta.to.shared.u64 t, %1; cvt.u32.u64 %0, t; }" : "=r"(a) : "l"(p));
    return a;
}
__device__ __forceinline__ float ex2f(float x) {
    float r; asm("ex2.approx.ftz.f32 %0, %1;" : "=f"(r) : "f"(x)); return r;
}
#define CP_ASYNC16(dst, src) \
    asm volatile("cp.async.cg.shared.global [%0], [%1], 16;" :: "r"(dst), "l"(src))
#define CP_COMMIT() asm volatile("cp.async.commit_group;" ::: "memory")
#define CP_WAIT(n)  asm volatile("cp.async.wait_group %0;" :: "n"(n) : "memory")

__device__ __forceinline__ void ldsm4(uint32_t* r, uint32_t addr) {
    asm volatile("ldmatrix.sync.aligned.m8n8.x4.shared.b16 {%0,%1,%2,%3}, [%4];"
                 : "=r"(r[0]), "=r"(r[1]), "=r"(r[2]), "=r"(r[3]) : "r"(addr));
}
__device__ __forceinline__ void mma_bf16(float* c, const uint32_t* a, const uint32_t* b) {
    asm volatile(
        "mma.sync.aligned.m16n8k16.row.col.f32.bf16.bf16.f32 "
        "{%0,%1,%2,%3}, {%4,%5,%6,%7}, {%8,%9}, {%0,%1,%2,%3};"
        : "+f"(c[0]), "+f"(c[1]), "+f"(c[2]), "+f"(c[3])
        : "r"(a[0]), "r"(a[1]), "r"(a[2]), "r"(a[3]), "r"(b[0]), "r"(b[1]));
}

// ---------------------------------------------------------------------------
// Kernel 1: L2-normalize -> bf16, pre-scaled by sqrt(C_EX2). One warp per row.
// ---------------------------------------------------------------------------
__global__ void norm_bf16_kernel(const float* __restrict__ emb_i,
                                 const float* __restrict__ emb_j) {
    int warp = (blockIdx.x * blockDim.x + threadIdx.x) >> 5;
    int lane = threadIdx.x & 31;
    if (warp >= LAYERS * TWON) return;
    int layer = warp >> 12;
    int row   = warp & (TWON - 1);

    const float* src = (row < N_)
        ? (emb_i + ((size_t)layer * N_ + row) * D_)
        : (emb_j + ((size_t)layer * N_ + (row - N_)) * D_);

    float4 v = ((const float4*)src)[lane];
    float s = v.x * v.x + v.y * v.y + v.z * v.z + v.w * v.w;
    #pragma unroll
    for (int o = 16; o > 0; o >>= 1) s += __shfl_xor_sync(0xffffffffu, s, o);

    float inv = SQC * rsqrtf(fmaxf(s, EPS * EPS));
    uint2 u;
    u.x = (uint32_t)__bfloat16_as_ushort(__float2bfloat16(v.x * inv))
        | ((uint32_t)__bfloat16_as_ushort(__float2bfloat16(v.y * inv)) << 16);
    u.y = (uint32_t)__bfloat16_as_ushort(__float2bfloat16(v.z * inv))
        | ((uint32_t)__bfloat16_as_ushort(__float2bfloat16(v.w * inv)) << 16);
    ((uint2*)(g_zb + ((size_t)layer * TWON + row) * D_))[lane] = u;
}

// ---------------------------------------------------------------------------
// Kernel 2: symmetric fused Gram + exp.  296 CTAs x 256 threads, 2 CTAs/SM.
// Dynamic work-stealing: CTA's first op = blockIdx.x; subsequent ops come
// from an atomic ticket grabbed ONE OP AHEAD (published by the existing
// barriers, zero extra syncs).  All writes are to disjoint slots with
// scheduling-independent values -> deterministic.
// ---------------------------------------------------------------------------
extern __shared__ char dsm[];

__device__ __forceinline__ void unrank(int t, int& layer, int& ib, int& jb) {
    layer = t / TOPSL;
    int rem = t - layer * TOPSL;
    int i = 0;
    while (rem >= NTILE - i) { rem -= NTILE - i; ++i; }
    ib = i; jb = i + rem;
}

__device__ __forceinline__ void load_pair(int layer, int ib, int jb,
                                          uint32_t base, int tid) {
    const __nv_bfloat16* Z = g_zb + (size_t)layer * TWON * D_;
    const __nv_bfloat16* Ai = Z + (size_t)ib * 128 * D_;
    const __nv_bfloat16* Bj = Z + (size_t)jb * 128 * D_;
    #pragma unroll
    for (int p = 0; p < 8; ++p) {
        int idx = p * 256 + tid;               // 2048 16B segs per tile
        int r = idx >> 4, sc = idx & 15;
        CP_ASYNC16(base + r * SROWB + sc * 16,
                   (const char*)(Ai + (size_t)r * D_) + sc * 16);
        CP_ASYNC16(base + TILEB + r * SROWB + sc * 16,
                   (const char*)(Bj + (size_t)r * D_) + sc * 16);
    }
}

__global__ void __launch_bounds__(256, 2) sim_sym_kernel() {
    __shared__ float red_r[2][128];
    __shared__ float red_c[4][128];
    __shared__ int   s_next[2];

    int tid  = threadIdx.x;
    int wid  = tid >> 5;
    int lane = tid & 31;
    int warpRow = wid & 3;      // 4 slices of 32 rows
    int warpCol = wid >> 2;     // 2 slices of 64 cols

    uint32_t sb = (smem_u32(dsm) + 1023) & ~1023u;
    uint32_t buf = sb;

    uint32_t laneA = (uint32_t)((lane & 7) * SROWB + ((lane >> 3) & 1) * (8 * SROWB)
                                + ((lane >> 4) & 1) * 16);
    uint32_t laneB = (uint32_t)((lane & 7) * SROWB + ((lane >> 3) & 1) * 16
                                + ((lane >> 4) & 1) * (8 * SROWB));

    int t = (int)blockIdx.x;    // first op is static (no counter burst)
    int it = 0;

    while (t < TOTOPS) {
        // Grab NEXT ticket early; published by the post-load barrier below.
        if (tid == 0) s_next[it & 1] = (int)atomicAdd(&g_tick, 1u);

        int layer, ib, jb;
        unrank(t, layer, ib, jb);

        load_pair(layer, ib, jb, buf, tid);
        CP_COMMIT();
        CP_WAIT(0);
        __syncthreads();            // buf ready; red free; s_next published

        uint32_t aA = buf + (uint32_t)(warpRow * 32 * SROWB) + laneA;
        uint32_t bA = buf + TILEB + (uint32_t)(warpCol * 64 * SROWB) + laneB;

        float acc[2][8][4];
        #pragma unroll
        for (int mt = 0; mt < 2; ++mt)
            #pragma unroll
            for (int nt = 0; nt < 8; ++nt)
                #pragma unroll
                for (int ci = 0; ci < 4; ++ci) acc[mt][nt][ci] = 0.f;

        #pragma unroll
        for (int kt = 0; kt < 8; ++kt) {
            uint32_t aF0[4], aF1[4];
            ldsm4(aF0, aA + (uint32_t)(kt * 32));
            ldsm4(aF1, aA + (uint32_t)(16 * SROWB + kt * 32));
            #pragma unroll
            for (int np = 0; np < 4; ++np) {
                uint32_t tt[4];
                ldsm4(tt, bA + (uint32_t)(np * 16 * SROWB + kt * 32));
                mma_bf16(acc[0][2 * np],     aF0, &tt[0]);
                mma_bf16(acc[0][2 * np + 1], aF0, &tt[2]);
                mma_bf16(acc[1][2 * np],     aF1, &tt[0]);
                mma_bf16(acc[1][2 * np + 1], aF1, &tt[2]);
            }
        }

        // ---- epilogue: exp, row-sums, col-sums, diagonal captures ----
        bool isDiag = (ib == jb);
        bool isPos  = (jb == ib + (N_ / 128));

        float dsum[4] = {0.f, 0.f, 0.f, 0.f};
        float csum[16];
        #pragma unroll
        for (int x = 0; x < 16; ++x) csum[x] = 0.f;

        #pragma unroll
        for (int mt = 0; mt < 2; ++mt)
            #pragma unroll
            for (int nt = 0; nt < 8; ++nt)
                #pragma unroll
                for (int ci = 0; ci < 4; ++ci) {
                    float s = acc[mt][nt][ci];       // already C_EX2-scaled
                    float e = ex2f(s);
                    dsum[mt * 2 + (ci >> 1)] += e;
                    csum[nt * 2 + (ci & 1)] += e;
                    if (isDiag | isPos) {
                        int rl = warpRow * 32 + (lane >> 2) + mt * 16 + (ci >> 1) * 8;
                        int cl = warpCol * 64 + nt * 8 + (lane & 3) * 2 + (ci & 1);
                        if (rl == cl) {
                            if (isDiag) g_diag[layer * TWON + ib * 128 + rl] = s;
                            else        g_posv[layer * N_   + ib * 128 + rl] = s;
                        }
                    }
                }

        // row reduction: over lane&3
        #pragma unroll
        for (int ri = 0; ri < 4; ++ri) {
            #pragma unroll
            for (int o = 1; o <= 2; o <<= 1)
                dsum[ri] += __shfl_xor_sync(0xffffffffu, dsum[ri], o);
        }
        if ((lane & 3) == 0) {
            #pragma unroll
            for (int ri = 0; ri < 4; ++ri) {
                int rloc = warpRow * 32 + (ri >> 1) * 16 + (ri & 1) * 8 + (lane >> 2);
                red_r[warpCol][rloc] = dsum[ri];
            }
        }
        // col reduction: over lane>>2 (xor 4,8,16)
        #pragma unroll
        for (int x = 0; x < 16; ++x) {
            #pragma unroll
            for (int o = 4; o <= 16; o <<= 1)
                csum[x] += __shfl_xor_sync(0xffffffffu, csum[x], o);
        }
        if (lane < 4) {
            #pragma unroll
            for (int x = 0; x < 16; ++x) {
                int cl = warpCol * 64 + (x >> 1) * 8 + lane * 2 + (x & 1);
                red_c[warpRow][cl] = csum[x];
            }
        }
        __syncthreads();            // red complete; buf reads complete

        if (tid < 128) {
            float rs = red_r[0][tid] + red_r[1][tid];
            g_acc[(((size_t)layer * NTILE + ib) * NTILE + jb) * 128 + tid] = rs;
        } else if (!isDiag) {
            int c = tid - 128;
            float cs = red_c[0][c] + red_c[1][c] + red_c[2][c] + red_c[3][c];
            g_acc[(((size_t)layer * NTILE + jb) * NTILE + ib) * 128 + c] = cs;
        }
        // next iteration's top barrier orders flush before red rewrite

        t = s_next[it & 1];
        ++it;
    }
}

// ---------------------------------------------------------------------------
// Kernel 3: lp + mask + block partials + fused last-block final combine.
// Last block also resets the work-stealing ticket for the next graph replay.
// ---------------------------------------------------------------------------
__global__ void lp_reduce_kernel(const float* __restrict__ joint_valid,
                                 float* __restrict__ out) {
    __shared__ float s1[256];
    __shared__ unsigned int isLast;
    int tid  = threadIdx.x;
    int ridx = blockIdx.x * 256 + tid;     // [0, LAYERS*TWON)
    int layer = ridx >> 12;
    int r     = ridx & (TWON - 1);
    int blk   = r >> 7;
    int rl    = r & 127;

    const float* slots = g_acc + (((size_t)layer * NTILE + blk) * NTILE) * 128 + rl;
    float d = 0.f;
    #pragma unroll
    for (int k = 0; k < NTILE; ++k) d += slots[k * 128];

    float denom = d - ex2f(g_diag[ridx]);                 // remove self term
    float posac = g_posv[layer * N_ + (r & (N_ - 1))];    // C*s_pos
    float lp = logf(denom) - posac * LN2F;

    s1[tid] = lp * joint_valid[r & (N_ - 1)];
    __syncthreads();
    #pragma unroll
    for (int s = 128; s > 0; s >>= 1) {
        if (tid < s) s1[tid] += s1[tid + s];
        __syncthreads();
    }
    if (tid == 0) {
        g_part[blockIdx.x] = s1[0];
        __threadfence();
        unsigned int prev = atomicAdd(&g_ctr, 1u);
        isLast = (prev == RBLK - 1) ? 1u : 0u;
    }
    __syncthreads();

    if (isLast) {
        __threadfence();                  // see all g_part writes
        float tpart = (tid < RBLK) ? g_part[tid] : 0.f;
        float an = 0.f;
        #pragma unroll
        for (int k = 0; k < N_ / 256; ++k) an += joint_valid[k * 256 + tid];

        __shared__ float s2[256];
        s1[tid] = tpart;
        s2[tid] = an;
        __syncthreads();
        #pragma unroll
        for (int s = 128; s > 0; s >>= 1) {
            if (tid < s) { s1[tid] += s1[tid + s]; s2[tid] += s2[tid + s]; }
            __syncthreads();
        }
        if (tid == 0) {
            out[0] = s1[0] / (2.0f * s2[0]);
            g_ctr  = 0u;                  // reset for next graph replay
            g_tick = NCTA;                // reset ticket counter
        }
    }
}

// ---------------------------------------------------------------------------
extern "C" void kernel_launch(void* const* d_in, const int* in_sizes, int n_in,
                              void* d_out, int out_size) {
    const float* emb_i       = (const float*)d_in[0];
    const float* emb_j       = (const float*)d_in[1];
    const float* joint_valid = (const float*)d_in[2];
    float* out = (float*)d_out;
    (void)in_sizes; (void)n_in; (void)out_size;

    const int SIM_SMEM = 1024 + 2 * TILEB;   // one A+B pair = 70656 B
    cudaFuncSetAttribute(sim_sym_kernel, cudaFuncAttributeMaxDynamicSharedMemorySize, SIM_SMEM);

    norm_bf16_kernel<<<(LAYERS * TWON) / 8, 256>>>(emb_i, emb_j);
    sim_sym_kernel<<<NCTA, 256, SIM_SMEM>>>();
    lp_reduce_kernel<<<RBLK, 256>>>(joint_valid, out);
}

// round 15
// speedup vs baseline: 1.6034x; 1.0471x over previous
#include <cuda_runtime.h>
#include <cuda_bf16.h>
#include <math.h>
#include <stdint.h>

// Problem constants
#define LAYERS 4
#define D_     128
#define N_     2048
#define TWON   4096
#define INV_T  5.0f
#define EPS    1e-12f
#define C_EX2  7.21347520444481703076f   // (1/T) * log2(e)
#define SQC    2.68579079f               // sqrt(C_EX2); z stored as z*SQC => acc = C_EX2*s
#define LN2F   0.69314718056f            // INV_T / C_EX2

#define SROWB  272                       // smem row stride bytes (128 bf16 + 16B pad)
#define TILEB  (128 * SROWB)             // 34816
#define NTILE  32                        // 4096/128 blocks per layer
#define TOPSL  528                       // NTILE*(NTILE+1)/2 tile-ops per layer
#define TOTOPS (LAYERS * TOPSL)          // 2112
#define NCTA   296                       // 2 CTAs per SM
#define RUNLEN 7                         // static contiguous ops per CTA (296*7=2072)
#define TAIL0  (NCTA * RUNLEN)           // 2072; tail ops 2072..2111 are stolen
#define RBLK   64                        // reduction blocks (16384 rows / 256)

// Scratch
__device__ __align__(256) __nv_bfloat16 g_zb[LAYERS * TWON * D_];
__device__ float g_acc[LAYERS * NTILE * NTILE * 128];  // [l][i][j][rl] exp-sums (2MB)
__device__ float g_diag[LAYERS * TWON];                // scaled diag acc (C*s_ii)
__device__ float g_posv[LAYERS * N_];                  // scaled pos acc (C*s_pos)
__device__ float g_part[RBLK];                         // per-block masked partials
__device__ unsigned int g_ctr;                         // last-block counter (self-resetting)
__device__ unsigned int g_tick;                        // tail ticket (reset by lp_reduce)

// ---------------------------------------------------------------------------
__device__ __forceinline__ uint32_t smem_u32(const void* p) {
    uint32_t a;
    asm("{ .reg .u64 t; cvta.to.shared.u64 t, %1; cvt.u32.u64 %0, t; }" : "=r"(a) : "l"(p));
    return a;
}
__device__ __forceinline__ float ex2f(float x) {
    float r; asm("ex2.approx.ftz.f32 %0, %1;" : "=f"(r) : "f"(x)); return r;
}
#define CP_ASYNC16(dst, src) \
    asm volatile("cp.async.cg.shared.global [%0], [%1], 16;" :: "r"(dst), "l"(src))
#define CP_COMMIT() asm volatile("cp.async.commit_group;" ::: "memory")
#define CP_WAIT(n)  asm volatile("cp.async.wait_group %0;" :: "n"(n) : "memory")

__device__ __forceinline__ void ldsm4(uint32_t* r, uint32_t addr) {
    asm volatile("ldmatrix.sync.aligned.m8n8.x4.shared.b16 {%0,%1,%2,%3}, [%4];"
                 : "=r"(r[0]), "=r"(r[1]), "=r"(r[2]), "=r"(r[3]) : "r"(addr));
}
__device__ __forceinline__ void mma_bf16(float* c, const uint32_t* a, const uint32_t* b) {
    asm volatile(
        "mma.sync.aligned.m16n8k16.row.col.f32.bf16.bf16.f32 "
        "{%0,%1,%2,%3}, {%4,%5,%6,%7}, {%8,%9}, {%0,%1,%2,%3};"
        : "+f"(c[0]), "+f"(c[1]), "+f"(c[2]), "+f"(c[3])
        : "r"(a[0]), "r"(a[1]), "r"(a[2]), "r"(a[3]), "r"(b[0]), "r"(b[1]));
}

// ---------------------------------------------------------------------------
// Kernel 1: L2-normalize -> bf16, pre-scaled by sqrt(C_EX2). One warp per row.
// ---------------------------------------------------------------------------
__global__ void norm_bf16_kernel(const float* __restrict__ emb_i,
                                 const float* __restrict__ emb_j) {
    int warp = (blockIdx.x * blockDim.x + threadIdx.x) >> 5;
    int lane = threadIdx.x & 31;
    if (warp >= LAYERS * TWON) return;
    int layer = warp >> 12;
    int row   = warp & (TWON - 1);

    const float* src = (row < N_)
        ? (emb_i + ((size_t)layer * N_ + row) * D_)
        : (emb_j + ((size_t)layer * N_ + (row - N_)) * D_);

    float4 v = ((const float4*)src)[lane];
    float s = v.x * v.x + v.y * v.y + v.z * v.z + v.w * v.w;
    #pragma unroll
    for (int o = 16; o > 0; o >>= 1) s += __shfl_xor_sync(0xffffffffu, s, o);

    float inv = SQC * rsqrtf(fmaxf(s, EPS * EPS));
    uint2 u;
    u.x = (uint32_t)__bfloat16_as_ushort(__float2bfloat16(v.x * inv))
        | ((uint32_t)__bfloat16_as_ushort(__float2bfloat16(v.y * inv)) << 16);
    u.y = (uint32_t)__bfloat16_as_ushort(__float2bfloat16(v.z * inv))
        | ((uint32_t)__bfloat16_as_ushort(__float2bfloat16(v.w * inv)) << 16);
    ((uint2*)(g_zb + ((size_t)layer * TWON + row) * D_))[lane] = u;
}

// ---------------------------------------------------------------------------
// Kernel 2: symmetric fused Gram + exp.  296 CTAs x 256 threads, 2 CTAs/SM.
// Static contiguous 7-op runs (A-block resident, B double-buffered+prefetched)
// plus a 40-op stolen tail for load balance.
// SMEM/CTA: A + 2xB = 105 KB -> 210 KB/SM, occupancy 2.
// ---------------------------------------------------------------------------
extern __shared__ char dsm[];

__device__ __forceinline__ void unrank(int t, int& layer, int& ib, int& jb) {
    layer = t / TOPSL;
    int rem = t - layer * TOPSL;
    int i = 0;
    while (rem >= NTILE - i) { rem -= NTILE - i; ++i; }
    ib = i; jb = i + rem;
}

// Load one 128x128 bf16 block into a tile buffer.
__device__ __forceinline__ void load_tile(int layer, int blk, uint32_t base, int tid) {
    const __nv_bfloat16* P = g_zb + (size_t)layer * TWON * D_ + (size_t)blk * 128 * D_;
    #pragma unroll
    for (int p = 0; p < 8; ++p) {
        int idx = p * 256 + tid;               // 2048 16B segs
        int r = idx >> 4, sc = idx & 15;
        CP_ASYNC16(base + r * SROWB + sc * 16,
                   (const char*)(P + (size_t)r * D_) + sc * 16);
    }
}

struct OpCtx {
    int layer, ib, jb;
};

// Compute one tile-op from bufA/bufB, reduce, and flush (two barriers inside).
__device__ __forceinline__ void do_op(const OpCtx& op, uint32_t bufA, uint32_t bufB,
                                      int tid, int lane, int warpRow, int warpCol,
                                      uint32_t laneA, uint32_t laneB,
                                      float (*red_r)[128], float (*red_c)[128]) {
    uint32_t aA = bufA + (uint32_t)(warpRow * 32 * SROWB) + laneA;
    uint32_t bA = bufB + (uint32_t)(warpCol * 64 * SROWB) + laneB;

    float acc[2][8][4];
    #pragma unroll
    for (int mt = 0; mt < 2; ++mt)
        #pragma unroll
        for (int nt = 0; nt < 8; ++nt)
            #pragma unroll
            for (int ci = 0; ci < 4; ++ci) acc[mt][nt][ci] = 0.f;

    #pragma unroll
    for (int kt = 0; kt < 8; ++kt) {
        uint32_t aF0[4], aF1[4];
        ldsm4(aF0, aA + (uint32_t)(kt * 32));
        ldsm4(aF1, aA + (uint32_t)(16 * SROWB + kt * 32));
        #pragma unroll
        for (int np = 0; np < 4; ++np) {
            uint32_t tt[4];
            ldsm4(tt, bA + (uint32_t)(np * 16 * SROWB + kt * 32));
            mma_bf16(acc[0][2 * np],     aF0, &tt[0]);
            mma_bf16(acc[0][2 * np + 1], aF0, &tt[2]);
            mma_bf16(acc[1][2 * np],     aF1, &tt[0]);
            mma_bf16(acc[1][2 * np + 1], aF1, &tt[2]);
        }
    }

    bool isDiag = (op.ib == op.jb);
    bool isPos  = (op.jb == op.ib + (N_ / 128));

    float dsum[4] = {0.f, 0.f, 0.f, 0.f};
    float csum[16];
    #pragma unroll
    for (int x = 0; x < 16; ++x) csum[x] = 0.f;

    #pragma unroll
    for (int mt = 0; mt < 2; ++mt)
        #pragma unroll
        for (int nt = 0; nt < 8; ++nt)
            #pragma unroll
            for (int ci = 0; ci < 4; ++ci) {
                float s = acc[mt][nt][ci];       // already C_EX2-scaled
                float e = ex2f(s);
                dsum[mt * 2 + (ci >> 1)] += e;
                csum[nt * 2 + (ci & 1)] += e;
                if (isDiag | isPos) {
                    int rl = warpRow * 32 + (lane >> 2) + mt * 16 + (ci >> 1) * 8;
                    int cl = warpCol * 64 + nt * 8 + (lane & 3) * 2 + (ci & 1);
                    if (rl == cl) {
                        if (isDiag) g_diag[op.layer * TWON + op.ib * 128 + rl] = s;
                        else        g_posv[op.layer * N_   + op.ib * 128 + rl] = s;
                    }
                }
            }

    // row reduction: over lane&3
    #pragma unroll
    for (int ri = 0; ri < 4; ++ri) {
        #pragma unroll
        for (int o = 1; o <= 2; o <<= 1)
            dsum[ri] += __shfl_xor_sync(0xffffffffu, dsum[ri], o);
    }
    if ((lane & 3) == 0) {
        #pragma unroll
        for (int ri = 0; ri < 4; ++ri) {
            int rloc = warpRow * 32 + (ri >> 1) * 16 + (ri & 1) * 8 + (lane >> 2);
            red_r[warpCol][rloc] = dsum[ri];
        }
    }
    // col reduction: over lane>>2
    #pragma unroll
    for (int x = 0; x < 16; ++x) {
        #pragma unroll
        for (int o = 4; o <= 16; o <<= 1)
            csum[x] += __shfl_xor_sync(0xffffffffu, csum[x], o);
    }
    if (lane < 4) {
        #pragma unroll
        for (int x = 0; x < 16; ++x) {
            int cl = warpCol * 64 + (x >> 1) * 8 + lane * 2 + (x & 1);
            red_c[warpRow][cl] = csum[x];
        }
    }
    __syncthreads();            // red complete; all smem tile reads complete

    if (tid < 128) {
        float rs = red_r[0][tid] + red_r[1][tid];
        g_acc[(((size_t)op.layer * NTILE + op.ib) * NTILE + op.jb) * 128 + tid] = rs;
    } else if (!isDiag) {
        int c = tid - 128;
        float cs = red_c[0][c] + red_c[1][c] + red_c[2][c] + red_c[3][c];
        g_acc[(((size_t)op.layer * NTILE + op.jb) * NTILE + op.ib) * 128 + c] = cs;
    }
    // caller's next top barrier orders this flush before red rewrite
}

__global__ void __launch_bounds__(256, 2) sim_sym_kernel() {
    __shared__ float red_r[2][128];
    __shared__ float red_c[4][128];

    int tid  = threadIdx.x;
    int wid  = tid >> 5;
    int lane = tid & 31;
    int warpRow = wid & 3;      // 4 slices of 32 rows
    int warpCol = wid >> 2;     // 2 slices of 64 cols

    uint32_t sb = (smem_u32(dsm) + 1023) & ~1023u;
    uint32_t bufA = sb;
    uint32_t bufB[2] = { sb + TILEB, sb + 2 * TILEB };

    uint32_t laneA = (uint32_t)((lane & 7) * SROWB + ((lane >> 3) & 1) * (8 * SROWB)
                                + ((lane >> 4) & 1) * 16);
    uint32_t laneB = (uint32_t)((lane & 7) * SROWB + ((lane >> 3) & 1) * 16
                                + ((lane >> 4) & 1) * (8 * SROWB));

    // ---- static run: ops [c*7, c*7+7) ----
    int start = (int)blockIdx.x * RUNLEN;
    OpCtx cur, nxt;
    unrank(start, cur.layer, cur.ib, cur.jb);

    load_tile(cur.layer, cur.ib, bufA, tid);
    load_tile(cur.layer, cur.jb, bufB[0], tid);
    CP_COMMIT();

    int p = 0;
    #pragma unroll 1
    for (int k = 0; k < RUNLEN; ++k) {
        int tcur = start + k;
        int haveNext = (k + 1 < RUNLEN);
        if (haveNext) unrank(tcur + 1, nxt.layer, nxt.ib, nxt.jb);

        CP_WAIT(0);
        bool crossing = haveNext && (nxt.ib != cur.ib || nxt.layer != cur.layer);
        __syncthreads();        // bufA/bufB[p] ready; red free; prior flush done

        // Prefetch next B into alternate buffer (drains under compute).
        if (haveNext) {
            load_tile(nxt.layer, nxt.jb, bufB[p ^ 1], tid);
            CP_COMMIT();
        }

        do_op(cur, bufA, bufB[p], tid, lane, warpRow, warpCol, laneA, laneB,
              red_r, red_c);

        if (haveNext) {
            if (crossing) {
                // rare: new A row — blocking load after all A reads finished
                // (do_op's internal end barrier guarantees that).
                CP_WAIT(0);     // B prefetch first (keeps groups simple)
                load_tile(nxt.layer, nxt.ib, bufA, tid);
                CP_COMMIT();
            }
            cur = nxt;
            p ^= 1;
        }
    }

    // ---- stolen tail: ops TAIL0..TOTOPS-1, blocking loads ----
    __shared__ int s_t;
    while (true) {
        __syncthreads();        // protects s_t reuse + red arrays + buffers
        if (tid == 0) s_t = TAIL0 + (int)atomicAdd(&g_tick, 1u);
        __syncthreads();
        int t = s_t;
        if (t >= TOTOPS) break;

        OpCtx op;
        unrank(t, op.layer, op.ib, op.jb);
        load_tile(op.layer, op.ib, bufA, tid);
        load_tile(op.layer, op.jb, bufB[0], tid);
        CP_COMMIT();
        CP_WAIT(0);
        __syncthreads();

        do_op(op, bufA, bufB[0], tid, lane, warpRow, warpCol, laneA, laneB,
              red_r, red_c);
    }
}

// ---------------------------------------------------------------------------
// Kernel 3: lp + mask + block partials + fused last-block final combine.
// Last block also resets the tail ticket for the next graph replay.
// ---------------------------------------------------------------------------
__global__ void lp_reduce_kernel(const float* __restrict__ joint_valid,
                                 float* __restrict__ out) {
    __shared__ float s1[256];
    __shared__ unsigned int isLast;
    int tid  = threadIdx.x;
    int ridx = blockIdx.x * 256 + tid;     // [0, LAYERS*TWON)
    int layer = ridx >> 12;
    int r     = ridx & (TWON - 1);
    int blk   = r >> 7;
    int rl    = r & 127;

    const float* slots = g_acc + (((size_t)layer * NTILE + blk) * NTILE) * 128 + rl;
    float d = 0.f;
    #pragma unroll
    for (int k = 0; k < NTILE; ++k) d += slots[k * 128];

    float denom = d - ex2f(g_diag[ridx]);                 // remove self term
    float posac = g_posv[layer * N_ + (r & (N_ - 1))];    // C*s_pos
    float lp = logf(denom) - posac * LN2F;

    s1[tid] = lp * joint_valid[r & (N_ - 1)];
    __syncthreads();
    #pragma unroll
    for (int s = 128; s > 0; s >>= 1) {
        if (tid < s) s1[tid] += s1[tid + s];
        __syncthreads();
    }
    if (tid == 0) {
        g_part[blockIdx.x] = s1[0];
        __threadfence();
        unsigned int prev = atomicAdd(&g_ctr, 1u);
        isLast = (prev == RBLK - 1) ? 1u : 0u;
    }
    __syncthreads();

    if (isLast) {
        __threadfence();                  // see all g_part writes
        float tpart = (tid < RBLK) ? g_part[tid] : 0.f;
        float an = 0.f;
        #pragma unroll
        for (int k = 0; k < N_ / 256; ++k) an += joint_valid[k * 256 + tid];

        __shared__ float s2[256];
        s1[tid] = tpart;
        s2[tid] = an;
        __syncthreads();
        #pragma unroll
        for (int s = 128; s > 0; s >>= 1) {
            if (tid < s) { s1[tid] += s1[tid + s]; s2[tid] += s2[tid + s]; }
            __syncthreads();
        }
        if (tid == 0) {
            out[0] = s1[0] / (2.0f * s2[0]);
            g_ctr  = 0u;                  // reset for next graph replay
            g_tick = 0u;                  // reset tail ticket
        }
    }
}

// ---------------------------------------------------------------------------
extern "C" void kernel_launch(void* const* d_in, const int* in_sizes, int n_in,
                              void* d_out, int out_size) {
    const float* emb_i       = (const float*)d_in[0];
    const float* emb_j       = (const float*)d_in[1];
    const float* joint_valid = (const float*)d_in[2];
    float* out = (float*)d_out;
    (void)in_sizes; (void)n_in; (void)out_size;

    const int SIM_SMEM = 1024 + 3 * TILEB;   // A + 2xB = 105472 B per CTA
    cudaFuncSetAttribute(sim_sym_kernel, cudaFuncAttributeMaxDynamicSharedMemorySize, SIM_SMEM);

    norm_bf16_kernel<<<(LAYERS * TWON) / 8, 256>>>(emb_i, emb_j);
    sim_sym_kernel<<<NCTA, 256, SIM_SMEM>>>();
    lp_reduce_kernel<<<RBLK, 256>>>(joint_valid, out);
}